// round 11
// baseline (speedup 1.0000x reference)
#include <cuda_runtime.h>
#include <cuda_bf16.h>
#include <stdint.h>

#define KNN 10
#define NPTS 2048
#define NB 8
#define BN_TOT (NB * NPTS)
#define LRELU(h) ((h) >= 0.f ? (h) : 0.2f * (h))

// ---------------- scratch (device globals; no runtime allocation) ----------------
__device__ float g_xcat[BN_TOT * 512];        // concat of out1..out4
__device__ float g_nrm[BN_TOT];
__device__ int   g_idx[BN_TOT * KNN];
__device__ float g_ycomb[BN_TOT * 512];       // [yd | yb] stacked cols (max 2*256)
__device__ int   g_poolI[NB * 1024];          // ordered-int max pool
__device__ float g_pts[BN_TOT * 4];
__device__ float g_w1d[64 * 4];
__device__ float g_w1b[64 * 4];
__device__ __nv_bfloat16 g_a3[BN_TOT * 1536]; // split A (hi|lo|hi), max Kp=1536
// W arena: [W5 | L4 | L3 | L2 | L1] split weights (per-layer [Wd-rows | Wb-rows])
#define OFF_W5 0
#define OFF_L4 1572864
#define OFF_L3 1769472
#define OFF_L2 1818624
#define OFF_L1 1843200
__device__ __nv_bfloat16 g_w3[1847296];

// ---------------- packed f32x2 helpers ---------------------------------------------
__device__ __forceinline__ void ffma2(unsigned long long& d,
                                      unsigned long long a, unsigned long long b)
{
    asm("fma.rn.f32x2 %0, %1, %2, %0;" : "+l"(d) : "l"(a), "l"(b));
}
__device__ __forceinline__ unsigned long long dup2(float a)
{
    unsigned long long p;
    asm("mov.b64 %0, {%1, %1};" : "=l"(p) : "f"(a));
    return p;
}
__device__ __forceinline__ float2 unpk(unsigned long long p)
{
    float2 f;
    asm("mov.b64 {%0, %1}, %2;" : "=f"(f.x), "=f"(f.y) : "l"(p));
    return f;
}

// ---------------- ordered-int float max encoding ------------------------------------
__device__ __forceinline__ int f2ord(float f)
{
    int i = __float_as_int(f);
    return i >= 0 ? i : (i ^ 0x7fffffff);
}
__device__ __forceinline__ float ord2f(int i)
{
    return __int_as_float(i >= 0 ? i : (i ^ 0x7fffffff));
}

// ---------------- mma.sync helpers -------------------------------------------------
__device__ __forceinline__ uint32_t smem_u32(const void* p)
{
    uint32_t a;
    asm("{ .reg .u64 t; cvta.to.shared.u64 t, %1; cvt.u32.u64 %0, t; }"
        : "=r"(a) : "l"(p));
    return a;
}
__device__ __forceinline__ void ldm_x4(uint32_t& r0, uint32_t& r1,
                                       uint32_t& r2, uint32_t& r3, uint32_t addr)
{
    asm volatile("ldmatrix.sync.aligned.m8n8.x4.shared.b16 {%0,%1,%2,%3}, [%4];"
                 : "=r"(r0), "=r"(r1), "=r"(r2), "=r"(r3) : "r"(addr));
}
__device__ __forceinline__ void mma_bf16(float* d, const uint32_t* a, const uint32_t* b)
{
    asm volatile(
        "mma.sync.aligned.m16n8k16.row.col.f32.bf16.bf16.f32 "
        "{%0,%1,%2,%3}, {%4,%5,%6,%7}, {%8,%9}, {%0,%1,%2,%3};"
        : "+f"(d[0]), "+f"(d[1]), "+f"(d[2]), "+f"(d[3])
        : "r"(a[0]), "r"(a[1]), "r"(a[2]), "r"(a[3]), "r"(b[0]), "r"(b[1]));
}

// ================= HMMA bf16 NT GEMM, optional fused max-pool =====================
#define HS 40
__global__ __launch_bounds__(256) void hgemm(
    const __nv_bfloat16* __restrict__ A, const __nv_bfloat16* __restrict__ B,
    float* __restrict__ C, int M, int N, int Kp, int ldc, int* __restrict__ poolI)
{
    __shared__ __nv_bfloat16 As[2][128][HS];
    __shared__ __nv_bfloat16 Bs[2][128][HS];
    const int tid = threadIdx.x;
    const int wid = tid >> 5, lane = tid & 31;
    const int wm = wid >> 2, wn = wid & 3;
    const int m0 = blockIdx.x * 128, n0 = blockIdx.y * 128;

    const int lrow = tid >> 2, lkc = (tid & 3) * 8;

    float acc[4][4][4];
#pragma unroll
    for (int i = 0; i < 4; i++)
#pragma unroll
        for (int j = 0; j < 4; j++)
#pragma unroll
            for (int q = 0; q < 4; q++) acc[i][j][q] = 0.f;

    uint4 va0, va1, vb0, vb1;
    const __nv_bfloat16* arow0 = A + (long long)(m0 + lrow) * Kp + lkc;
    const __nv_bfloat16* arow1 = arow0 + (long long)64 * Kp;
    const __nv_bfloat16* brow0 = B + (long long)(n0 + lrow) * Kp + lkc;
    const __nv_bfloat16* brow1 = brow0 + (long long)64 * Kp;

    va0 = *(const uint4*)(arow0);
    va1 = *(const uint4*)(arow1);
    vb0 = *(const uint4*)(brow0);
    vb1 = *(const uint4*)(brow1);
    *(uint4*)(&As[0][lrow][lkc]) = va0;
    *(uint4*)(&As[0][lrow + 64][lkc]) = va1;
    *(uint4*)(&Bs[0][lrow][lkc]) = vb0;
    *(uint4*)(&Bs[0][lrow + 64][lkc]) = vb1;
    __syncthreads();

    const int nc = Kp >> 5;

    const int arow_f = wm * 64 + (lane & 15);
    const int ahalf = (lane >> 4) * 8;
    const int bgrp = lane >> 3;
    const int brow_base = wn * 32 + (lane & 7);
    const int bhalf = (bgrp & 1) * 8;

    for (int c = 0; c < nc; c++) {
        const int cur = c & 1;
        if (c + 1 < nc) {
            const int k1 = (c + 1) * 32;
            va0 = *(const uint4*)(arow0 + k1);
            va1 = *(const uint4*)(arow1 + k1);
            vb0 = *(const uint4*)(brow0 + k1);
            vb1 = *(const uint4*)(brow1 + k1);
        }
#pragma unroll
        for (int ks = 0; ks < 2; ks++) {
            uint32_t af[4][4], bf[4][2];
#pragma unroll
            for (int mt = 0; mt < 4; mt++) {
                uint32_t ad = smem_u32(&As[cur][arow_f + mt * 16][ks * 16 + ahalf]);
                ldm_x4(af[mt][0], af[mt][1], af[mt][2], af[mt][3], ad);
            }
#pragma unroll
            for (int p = 0; p < 2; p++) {
                int brow = brow_base + (p * 2 + (bgrp >> 1)) * 8;
                uint32_t bd = smem_u32(&Bs[cur][brow][ks * 16 + bhalf]);
                ldm_x4(bf[p * 2][0], bf[p * 2][1], bf[p * 2 + 1][0], bf[p * 2 + 1][1], bd);
            }
#pragma unroll
            for (int mt = 0; mt < 4; mt++)
#pragma unroll
                for (int nt = 0; nt < 4; nt++)
                    mma_bf16(acc[mt][nt], af[mt], bf[nt]);
        }
        __syncthreads();
        if (c + 1 < nc) {
            const int nxt = (c + 1) & 1;
            *(uint4*)(&As[nxt][lrow][lkc]) = va0;
            *(uint4*)(&As[nxt][lrow + 64][lkc]) = va1;
            *(uint4*)(&Bs[nxt][lrow][lkc]) = vb0;
            *(uint4*)(&Bs[nxt][lrow + 64][lkc]) = vb1;
            __syncthreads();
        }
    }

    if (poolI == nullptr) {
#pragma unroll
        for (int mt = 0; mt < 4; mt++) {
            int row = m0 + wm * 64 + mt * 16 + (lane >> 2);
#pragma unroll
            for (int nt = 0; nt < 4; nt++) {
                int col = n0 + wn * 32 + nt * 8 + (lane & 3) * 2;
                *(float2*)(C + (long long)row * ldc + col) =
                    make_float2(acc[mt][nt][0], acc[mt][nt][1]);
                *(float2*)(C + (long long)(row + 8) * ldc + col) =
                    make_float2(acc[mt][nt][2], acc[mt][nt][3]);
            }
        }
    } else {
        float cm[4][2];
#pragma unroll
        for (int nt = 0; nt < 4; nt++) {
            float c0 = -3.4e38f, c1 = -3.4e38f;
#pragma unroll
            for (int mt = 0; mt < 4; mt++) {
                c0 = fmaxf(c0, fmaxf(acc[mt][nt][0], acc[mt][nt][2]));
                c1 = fmaxf(c1, fmaxf(acc[mt][nt][1], acc[mt][nt][3]));
            }
            cm[nt][0] = c0; cm[nt][1] = c1;
        }
#pragma unroll
        for (int off = 4; off <= 16; off <<= 1)
#pragma unroll
            for (int nt = 0; nt < 4; nt++) {
                cm[nt][0] = fmaxf(cm[nt][0], __shfl_xor_sync(0xffffffffu, cm[nt][0], off));
                cm[nt][1] = fmaxf(cm[nt][1], __shfl_xor_sync(0xffffffffu, cm[nt][1], off));
            }
        if ((lane >> 2) == 0) {
            int* pb = poolI + (m0 >> 11) * 1024;
#pragma unroll
            for (int nt = 0; nt < 4; nt++) {
                int col = n0 + wn * 32 + nt * 8 + (lane & 3) * 2;
                atomicMax(pb + col, f2ord(cm[nt][0]));
                atomicMax(pb + col + 1, f2ord(cm[nt][1]));
            }
        }
    }
}

// ---------------- pool init ---------------------------------------------------------
__global__ void pool_init(int* __restrict__ poolI)
{
    poolI[blockIdx.x * blockDim.x + threadIdx.x] = 0x80000000;
}

// ---------------- splits ------------------------------------------------------------
__global__ void split3_feat(const float* __restrict__ src, int lda, int C, int Kp,
                            __nv_bfloat16* __restrict__ dst, long long total)
{
    long long g = (long long)blockIdx.x * blockDim.x + threadIdx.x;
    if (g >= total) return;
    int k = (int)(g % Kp);
    long long m = g / Kp;
    if (k < 3 * C) {
        int seg = k / C, c = k - seg * C;
        float x = src[m * lda + c];
        __nv_bfloat16 hi = __float2bfloat16(x);
        if (seg == 1) dst[g] = __float2bfloat16(x - __bfloat162float(hi));
        else dst[g] = hi;
        return;
    }
    dst[g] = __float2bfloat16(0.f);
}
__global__ void split3_w(const float* __restrict__ src, int lds, int C, int Kp,
                         __nv_bfloat16* __restrict__ dst, int rowoff, long long total)
{
    long long g = (long long)blockIdx.x * blockDim.x + threadIdx.x;
    if (g >= total) return;
    int k = (int)(g % Kp);
    long long o = g / Kp;
    __nv_bfloat16* d = dst + (rowoff + o) * (long long)Kp + k;
    if (k < 3 * C) {
        int seg = k / C, c = k - seg * C;
        float x = src[o * lds + c];
        __nv_bfloat16 hi = __float2bfloat16(x);
        if (seg == 2) *d = __float2bfloat16(x - __bfloat162float(hi));
        else *d = hi;
        return;
    }
    *d = __float2bfloat16(0.f);
}
__global__ void split3_fast(const float* __restrict__ src, int lds, int lg2C,
                            __nv_bfloat16* __restrict__ dst, int isA, long long total)
{
    long long g = (long long)blockIdx.x * blockDim.x + threadIdx.x;
    if (g >= total) return;
    const int C = 1 << lg2C;
    long long m = g >> lg2C;
    int c = (int)(g & (C - 1));
    float x = src[m * lds + c];
    __nv_bfloat16 hi = __float2bfloat16(x);
    __nv_bfloat16 lo = __float2bfloat16(x - __bfloat162float(hi));
    __nv_bfloat16* d = dst + m * (3LL << lg2C);
    d[c] = hi;
    d[C + c] = isA ? lo : hi;
    d[2 * C + c] = isA ? hi : lo;
}

// ================= gram + knn v4: 8x8 micro-tile, 256 threads =====================
// As[k][m] (K x 128), Bs[k][j] (K x 128), stage (128 x 128 keys), stride 132.
// Per k: 4 LDS.128 + 8 dup + 32 FFMA2 (73% fma density). 2 syncs per j-tile.
// Scan: 2 threads/row, 64 cols each; 2-way (d, j) lexicographic merge (stable).
#define GK_SMEM_FLOATS (3 * 128 * 132)
#define GK_SMEM_BYTES (GK_SMEM_FLOATS * 4)
__global__ __launch_bounds__(256, 1) void gramknn8(
    const float* __restrict__ feat, int lda, int K,
    const float* __restrict__ nrm, int* __restrict__ idxout)
{
    extern __shared__ float sm[];
    float (*As)[132]    = reinterpret_cast<float(*)[132]>(sm);
    float (*Bs)[132]    = reinterpret_cast<float(*)[132]>(sm + 128 * 132);
    float (*stage)[132] = reinterpret_cast<float(*)[132]>(sm + 2 * 128 * 132);

    const int strip = blockIdx.x;
    const int b = blockIdx.y;
    const int i0 = strip * 128;
    const float* fb = feat + (long long)b * NPTS * lda;
    const float* nb = nrm + b * NPTS;
    const int tid = threadIdx.x;
    const int Kq = K >> 2;

    // A strip, k-major: 2 threads/row, Kq/2 float4 each
    {
        int m = tid >> 1;
        for (int q = tid & 1; q < Kq; q += 2) {
            float4 v = *(const float4*)(fb + (long long)(i0 + m) * lda + q * 4);
            As[q * 4 + 0][m] = v.x; As[q * 4 + 1][m] = v.y;
            As[q * 4 + 2][m] = v.z; As[q * 4 + 3][m] = v.w;
        }
    }

    const int cg = tid & 15;                 // cols cg*8..+7
    const int rg = tid >> 4;                 // rows rg*8..+7
    const int srow = tid & 127;              // scan: 2 threads/row
    const int sq = tid >> 7;                 // 0..1, 64 cols each
    const int self = i0 + srow;

    float bd[KNN];
    int bj[KNN];
#pragma unroll
    for (int p = 0; p < KNN; p++) { bd[p] = 3.4e38f; bj[p] = 0x7fffffff; }

    for (int jt = 0; jt < 16; jt++) {
        const int j0 = jt * 128;

        // B tile transposed: Bs[k][j]
        {
            int j = tid >> 1;
            for (int q = tid & 1; q < Kq; q += 2) {
                float4 v = *(const float4*)(fb + (long long)(j0 + j) * lda + q * 4);
                Bs[q * 4 + 0][j] = v.x; Bs[q * 4 + 1][j] = v.y;
                Bs[q * 4 + 2][j] = v.z; Bs[q * 4 + 3][j] = v.w;
            }
        }
        __syncthreads();   // A/B ready; also orders prev scan before stage overwrite

        unsigned long long acc[8][4];
#pragma unroll
        for (int r = 0; r < 8; r++)
#pragma unroll
            for (int p = 0; p < 4; p++) acc[r][p] = 0ull;

#pragma unroll 8
        for (int kk = 0; kk < K; kk++) {
            float4 a0 = *(const float4*)(&As[kk][rg * 8]);
            float4 a1 = *(const float4*)(&As[kk][rg * 8 + 4]);
            ulonglong2 b0 = *(const ulonglong2*)(&Bs[kk][cg * 8]);
            ulonglong2 b1 = *(const ulonglong2*)(&Bs[kk][cg * 8 + 4]);
            unsigned long long pa;
            pa = dup2(a0.x);
            ffma2(acc[0][0], pa, b0.x); ffma2(acc[0][1], pa, b0.y);
            ffma2(acc[0][2], pa, b1.x); ffma2(acc[0][3], pa, b1.y);
            pa = dup2(a0.y);
            ffma2(acc[1][0], pa, b0.x); ffma2(acc[1][1], pa, b0.y);
            ffma2(acc[1][2], pa, b1.x); ffma2(acc[1][3], pa, b1.y);
            pa = dup2(a0.z);
            ffma2(acc[2][0], pa, b0.x); ffma2(acc[2][1], pa, b0.y);
            ffma2(acc[2][2], pa, b1.x); ffma2(acc[2][3], pa, b1.y);
            pa = dup2(a0.w);
            ffma2(acc[3][0], pa, b0.x); ffma2(acc[3][1], pa, b0.y);
            ffma2(acc[3][2], pa, b1.x); ffma2(acc[3][3], pa, b1.y);
            pa = dup2(a1.x);
            ffma2(acc[4][0], pa, b0.x); ffma2(acc[4][1], pa, b0.y);
            ffma2(acc[4][2], pa, b1.x); ffma2(acc[4][3], pa, b1.y);
            pa = dup2(a1.y);
            ffma2(acc[5][0], pa, b0.x); ffma2(acc[5][1], pa, b0.y);
            ffma2(acc[5][2], pa, b1.x); ffma2(acc[5][3], pa, b1.y);
            pa = dup2(a1.z);
            ffma2(acc[6][0], pa, b0.x); ffma2(acc[6][1], pa, b0.y);
            ffma2(acc[6][2], pa, b1.x); ffma2(acc[6][3], pa, b1.y);
            pa = dup2(a1.w);
            ffma2(acc[7][0], pa, b0.x); ffma2(acc[7][1], pa, b0.y);
            ffma2(acc[7][2], pa, b1.x); ffma2(acc[7][3], pa, b1.y);
        }

        // rank keys d = nrm[j] - 2*dot -> stage
        float4 nj0 = *(const float4*)(nb + j0 + cg * 8);
        float4 nj1 = *(const float4*)(nb + j0 + cg * 8 + 4);
#pragma unroll
        for (int r = 0; r < 8; r++) {
            float2 p0 = unpk(acc[r][0]);
            float2 p1 = unpk(acc[r][1]);
            float2 p2 = unpk(acc[r][2]);
            float2 p3 = unpk(acc[r][3]);
            float4 d0, d1;
            d0.x = fmaf(-2.f, p0.x, nj0.x);
            d0.y = fmaf(-2.f, p0.y, nj0.y);
            d0.z = fmaf(-2.f, p1.x, nj0.z);
            d0.w = fmaf(-2.f, p1.y, nj0.w);
            d1.x = fmaf(-2.f, p2.x, nj1.x);
            d1.y = fmaf(-2.f, p2.y, nj1.y);
            d1.z = fmaf(-2.f, p3.x, nj1.z);
            d1.w = fmaf(-2.f, p3.y, nj1.w);
            *(float4*)(&stage[rg * 8 + r][cg * 8]) = d0;
            *(float4*)(&stage[rg * 8 + r][cg * 8 + 4]) = d1;
        }
        __syncthreads();

        // scan 64 cols via 16x float4 min-filter; scalar fallback on hit
#pragma unroll
        for (int q = 0; q < 16; q++) {
            int c4 = sq * 64 + q * 4;
            float4 v = *(const float4*)(&stage[srow][c4]);
            float m4 = fminf(fminf(v.x, v.y), fminf(v.z, v.w));
            if (m4 < bd[KNN - 1]) {
                float dv4[4] = {v.x, v.y, v.z, v.w};
#pragma unroll
                for (int e = 0; e < 4; e++) {
                    int j = j0 + c4 + e;
                    float d = dv4[e];
                    if (j != self && d < bd[KNN - 1]) {   // strict <: stable ties
                        bd[KNN - 1] = d; bj[KNN - 1] = j;
#pragma unroll
                        for (int p = KNN - 1; p > 0; p--) {
                            if (bd[p] < bd[p - 1]) {
                                float td = bd[p]; bd[p] = bd[p - 1]; bd[p - 1] = td;
                                int tj = bj[p]; bj[p] = bj[p - 1]; bj[p - 1] = tj;
                            }
                        }
                    }
                }
            }
        }
        // no trailing sync: next tile's post-load sync orders scan vs stage overwrite
    }
    __syncthreads();

    // dump lists (stride 22: d[0..9], sentinel@10, j@11..20, sentinel@21)
    float* mb = sm;
    {
        int base = (srow * 2 + sq) * 22;
#pragma unroll
        for (int p = 0; p < KNN; p++) {
            mb[base + p] = bd[p];
            ((int*)mb)[base + 11 + p] = bj[p];
        }
        mb[base + KNN] = 3.4e38f;
        ((int*)mb)[base + 11 + KNN] = 0x7fffffff;
    }
    __syncthreads();

    if (tid < 128) {
        int row = tid;
        int ptr[2] = {0, 0};
        int* outp = idxout + ((long long)(b * NPTS + i0 + row)) * KNN;
#pragma unroll
        for (int q = 0; q < KNN; q++) {
            float bestd = 3.4e38f; int bestj = 0x7fffffff; int bl = 0;
#pragma unroll
            for (int l = 0; l < 2; l++) {
                int base = (row * 2 + l) * 22;
                float dl = mb[base + ptr[l]];
                int jl = ((int*)mb)[base + 11 + ptr[l]];
                if (dl < bestd || (dl == bestd && jl < bestj)) {
                    bestd = dl; bestj = jl; bl = l;
                }
            }
            outp[q] = bestj;
            ptr[bl]++;
        }
    }
}

// ================= layer-1 fused gram + knn (FFMA2, K=4; from R8) =================
__global__ __launch_bounds__(512, 1) void gramknn(
    const float* __restrict__ feat, int lda, int K,
    const float* __restrict__ nrm, int* __restrict__ idxout)
{
    extern __shared__ float sm[];
    float (*As)[132]    = reinterpret_cast<float(*)[132]>(sm);
    float (*Bs)[132]    = reinterpret_cast<float(*)[132]>(sm + 128 * 132);
    float (*stage)[132] = reinterpret_cast<float(*)[132]>(sm + 2 * 128 * 132);

    const int strip = blockIdx.x;
    const int b = blockIdx.y;
    const int i0 = strip * 128;
    const float* fb = feat + (long long)b * NPTS * lda;
    const float* nb = nrm + b * NPTS;
    const int tid = threadIdx.x;

    for (int e = tid; e < K * 128; e += 512) {
        int k = e >> 7, m = e & 127;
        As[k][m] = fb[(long long)(i0 + m) * lda + k];
    }

    const int cg = tid & 31;
    const int rg = tid >> 5;
    const int srow = tid & 127;
    const int sq = tid >> 7;
    const int self = i0 + srow;
    const int Kq = K >> 2;

    float bd[KNN];
    int bj[KNN];
#pragma unroll
    for (int p = 0; p < KNN; p++) { bd[p] = 3.4e38f; bj[p] = 0x7fffffff; }

    for (int jt = 0; jt < 16; jt++) {
        const int j0 = jt * 128;

        for (int e = tid; e < 128 * Kq; e += 512) {
            int j = e / Kq;
            int kq = (e - j * Kq) * 4;
            float4 v = *(const float4*)(fb + (long long)(j0 + j) * lda + kq);
            Bs[kq + 0][j] = v.x; Bs[kq + 1][j] = v.y;
            Bs[kq + 2][j] = v.z; Bs[kq + 3][j] = v.w;
        }
        __syncthreads();

        unsigned long long acc[8][2];
#pragma unroll
        for (int r = 0; r < 8; r++) { acc[r][0] = 0ull; acc[r][1] = 0ull; }

#pragma unroll 4
        for (int kk = 0; kk < K; kk++) {
            float4 a0 = *(const float4*)(&As[kk][rg * 8]);
            float4 a1 = *(const float4*)(&As[kk][rg * 8 + 4]);
            ulonglong2 bb = *(const ulonglong2*)(&Bs[kk][cg * 4]);
            unsigned long long pa;
            pa = dup2(a0.x); ffma2(acc[0][0], pa, bb.x); ffma2(acc[0][1], pa, bb.y);
            pa = dup2(a0.y); ffma2(acc[1][0], pa, bb.x); ffma2(acc[1][1], pa, bb.y);
            pa = dup2(a0.z); ffma2(acc[2][0], pa, bb.x); ffma2(acc[2][1], pa, bb.y);
            pa = dup2(a0.w); ffma2(acc[3][0], pa, bb.x); ffma2(acc[3][1], pa, bb.y);
            pa = dup2(a1.x); ffma2(acc[4][0], pa, bb.x); ffma2(acc[4][1], pa, bb.y);
            pa = dup2(a1.y); ffma2(acc[5][0], pa, bb.x); ffma2(acc[5][1], pa, bb.y);
            pa = dup2(a1.z); ffma2(acc[6][0], pa, bb.x); ffma2(acc[6][1], pa, bb.y);
            pa = dup2(a1.w); ffma2(acc[7][0], pa, bb.x); ffma2(acc[7][1], pa, bb.y);
        }

        float4 nj = *(const float4*)(nb + j0 + cg * 4);
#pragma unroll
        for (int r = 0; r < 8; r++) {
            float2 lo = unpk(acc[r][0]);
            float2 hi = unpk(acc[r][1]);
            float4 dv;
            dv.x = fmaf(-2.f, lo.x, nj.x);
            dv.y = fmaf(-2.f, lo.y, nj.y);
            dv.z = fmaf(-2.f, hi.x, nj.z);
            dv.w = fmaf(-2.f, hi.y, nj.w);
            *(float4*)(&stage[rg * 8 + r][cg * 4]) = dv;
        }
        __syncthreads();

#pragma unroll
        for (int q = 0; q < 8; q++) {
            int c4 = sq * 32 + q * 4;
            float4 v = *(const float4*)(&stage[srow][c4]);
            float m4 = fminf(fminf(v.x, v.y), fminf(v.z, v.w));
            if (m4 < bd[KNN - 1]) {
                float dv4[4] = {v.x, v.y, v.z, v.w};
#pragma unroll
                for (int e = 0; e < 4; e++) {
                    int j = j0 + c4 + e;
                    float d = dv4[e];
                    if (j != self && d < bd[KNN - 1]) {
                        bd[KNN - 1] = d; bj[KNN - 1] = j;
#pragma unroll
                        for (int p = KNN - 1; p > 0; p--) {
                            if (bd[p] < bd[p - 1]) {
                                float td = bd[p]; bd[p] = bd[p - 1]; bd[p - 1] = td;
                                int tj = bj[p]; bj[p] = bj[p - 1]; bj[p - 1] = tj;
                            }
                        }
                    }
                }
            }
        }
    }
    __syncthreads();

    float* mb = sm;
    {
        int base = (srow * 4 + sq) * 24;
#pragma unroll
        for (int p = 0; p < KNN; p++) {
            mb[base + p] = bd[p];
            ((int*)mb)[base + 12 + p] = bj[p];
        }
        mb[base + KNN] = 3.4e38f;
        ((int*)mb)[base + 12 + KNN] = 0x7fffffff;
    }
    __syncthreads();

    if (tid < 128) {
        int row = tid;
        int ptr[4] = {0, 0, 0, 0};
        int* outp = idxout + ((long long)(b * NPTS + i0 + row)) * KNN;
#pragma unroll
        for (int q = 0; q < KNN; q++) {
            float bestd = 3.4e38f; int bestj = 0x7fffffff; int bl = 0;
#pragma unroll
            for (int l = 0; l < 4; l++) {
                int base = (row * 4 + l) * 24;
                float dl = mb[base + ptr[l]];
                int jl = ((int*)mb)[base + 12 + ptr[l]];
                if (dl < bestd || (dl == bestd && jl < bestj)) {
                    bestd = dl; bestj = jl; bl = l;
                }
            }
            outp[q] = bestj;
            ptr[bl]++;
        }
    }
}

// ---------------- row squared norms ------------------------------------------------
__global__ void rownorms(const float* __restrict__ feat, int lda, int C,
                         float* __restrict__ nrm)
{
    int g = blockIdx.x * blockDim.x + threadIdx.x;
    const float* p = feat + (long long)g * lda;
    float s = 0.f;
    for (int c = 0; c < C; c += 4) {
        float4 v = *(const float4*)(p + c);
        s += v.x * v.x + v.y * v.y + v.z * v.z + v.w * v.w;
    }
    nrm[g] = s;
}

// ---------------- combine (float4) --------------------------------------------------
__global__ void combine2(const float* __restrict__ ycomb,
                         const int* __restrict__ idx, const float* __restrict__ s,
                         const float* __restrict__ t, float* __restrict__ outx, int O)
{
    int g = blockIdx.x * blockDim.x + threadIdx.x;
    int q = O >> 2;
    int bn = g / q;
    int o = (g - bn * q) << 2;
    const int* ip = idx + (long long)bn * KNN;
    int base = bn & ~2047;
    const int ld = 2 * O;
    float4 m = make_float4(-3.4e38f, -3.4e38f, -3.4e38f, -3.4e38f);
#pragma unroll
    for (int k = 0; k < KNN; k++) {
        int j = ip[k];
        float4 v = *(const float4*)(ycomb + (long long)(base + j) * ld + o);
        m.x = fmaxf(m.x, v.x); m.y = fmaxf(m.y, v.y);
        m.z = fmaxf(m.z, v.z); m.w = fmaxf(m.w, v.w);
    }
    float4 ydv = *(const float4*)(ycomb + (long long)bn * ld + o);
    float4 ybv = *(const float4*)(ycomb + (long long)bn * ld + O + o);
    float4 sv = *(const float4*)(s + o);
    float4 tv = *(const float4*)(t + o);
    float4 h;
    h.x = (m.x - ydv.x + ybv.x) * sv.x + tv.x;
    h.y = (m.y - ydv.y + ybv.y) * sv.y + tv.y;
    h.z = (m.z - ydv.z + ybv.z) * sv.z + tv.z;
    h.w = (m.w - ydv.w + ybv.w) * sv.w + tv.w;
    h.x = LRELU(h.x); h.y = LRELU(h.y); h.z = LRELU(h.z); h.w = LRELU(h.w);
    *(float4*)(outx + (long long)bn * 512 + o) = h;
}

// ---------------- input padding helpers -------------------------------------------
__global__ void pad_pts(const float* __restrict__ p, float* __restrict__ pp)
{
    int g = blockIdx.x * blockDim.x + threadIdx.x;
    pp[g * 4 + 0] = p[g * 3 + 0];
    pp[g * 4 + 1] = p[g * 3 + 1];
    pp[g * 4 + 2] = p[g * 3 + 2];
    pp[g * 4 + 3] = 0.f;
}
__global__ void pad_w1(const float* __restrict__ W1, float* __restrict__ wd,
                       float* __restrict__ wb)
{
    int o = threadIdx.x;
#pragma unroll
    for (int c = 0; c < 3; c++) {
        wd[o * 4 + c] = W1[o * 6 + c];
        wb[o * 4 + c] = W1[o * 6 + 3 + c];
    }
    wd[o * 4 + 3] = 0.f;
    wb[o * 4 + 3] = 0.f;
}

// ---------------- final 3 FC layers, fused (reads ordered-int pool) ----------------
__global__ void final_fc(const int* __restrict__ poolI,
                         const float* __restrict__ s5, const float* __restrict__ t5,
                         const float* __restrict__ Wf1, const float* __restrict__ sf1,
                         const float* __restrict__ tf1,
                         const float* __restrict__ Wf2, const float* __restrict__ bf2,
                         const float* __restrict__ sf2, const float* __restrict__ tf2,
                         const float* __restrict__ Wf3, const float* __restrict__ bf3,
                         float* __restrict__ out)
{
    __shared__ float sx[1024];
    __shared__ float h1[512];
    __shared__ float h2[256];
    int b = blockIdx.x, tid = threadIdx.x;
    {
        float v0 = ord2f(poolI[b * 1024 + tid]) * s5[tid] + t5[tid];
        float v1 = ord2f(poolI[b * 1024 + tid + 512]) * s5[tid + 512] + t5[tid + 512];
        sx[tid] = LRELU(v0);
        sx[tid + 512] = LRELU(v1);
    }
    __syncthreads();
    {
        const float* w = Wf1 + (long long)tid * 1024;
        float a0 = 0.f, a1 = 0.f, a2 = 0.f, a3 = 0.f;
        for (int c = 0; c < 1024; c += 4) {
            a0 = fmaf(w[c + 0], sx[c + 0], a0);
            a1 = fmaf(w[c + 1], sx[c + 1], a1);
            a2 = fmaf(w[c + 2], sx[c + 2], a2);
            a3 = fmaf(w[c + 3], sx[c + 3], a3);
        }
        float h = ((a0 + a1) + (a2 + a3)) * sf1[tid] + tf1[tid];
        h1[tid] = LRELU(h);
    }
    __syncthreads();
    if (tid < 256) {
        const float* w = Wf2 + (long long)tid * 512;
        float a0 = 0.f, a1 = 0.f, a2 = 0.f, a3 = 0.f;
        for (int c = 0; c < 512; c += 4) {
            a0 = fmaf(w[c + 0], h1[c + 0], a0);
            a1 = fmaf(w[c + 1], h1[c + 1], a1);
            a2 = fmaf(w[c + 2], h1[c + 2], a2);
            a3 = fmaf(w[c + 3], h1[c + 3], a3);
        }
        float h = (((a0 + a1) + (a2 + a3)) + bf2[tid]) * sf2[tid] + tf2[tid];
        h2[tid] = LRELU(h);
    }
    __syncthreads();
    if (tid < 3) {
        const float* w = Wf3 + (long long)tid * 256;
        float a = 0.f;
        for (int c = 0; c < 256; c++) a = fmaf(w[c], h2[c], a);
        out[b * 3 + tid] = a + bf3[tid];
    }
}

// ------------------------------- host side ---------------------------------------
extern "C" void kernel_launch(void* const* d_in, const int* in_sizes, int n_in,
                              void* d_out, int out_size)
{
    const float* points = (const float*)d_in[0];
    const float* W1 = (const float*)d_in[1];  const float* s1 = (const float*)d_in[2];  const float* t1 = (const float*)d_in[3];
    const float* W2 = (const float*)d_in[4];  const float* s2 = (const float*)d_in[5];  const float* t2 = (const float*)d_in[6];
    const float* W3 = (const float*)d_in[7];  const float* s3 = (const float*)d_in[8];  const float* t3 = (const float*)d_in[9];
    const float* W4 = (const float*)d_in[10]; const float* s4 = (const float*)d_in[11]; const float* t4 = (const float*)d_in[12];
    const float* W5 = (const float*)d_in[13]; const float* s5 = (const float*)d_in[14]; const float* t5 = (const float*)d_in[15];
    const float* Wf1 = (const float*)d_in[16]; const float* sf1 = (const float*)d_in[17]; const float* tf1 = (const float*)d_in[18];
    const float* Wf2 = (const float*)d_in[19]; const float* bf2 = (const float*)d_in[20];
    const float* sf2 = (const float*)d_in[21]; const float* tf2 = (const float*)d_in[22];
    const float* Wf3 = (const float*)d_in[23]; const float* bf3 = (const float*)d_in[24];

    float *xcat, *nrm, *ycomb, *pts, *w1d, *w1b;
    int *idx, *poolI;
    __nv_bfloat16 *a3, *w3;
    cudaGetSymbolAddress((void**)&xcat,  g_xcat);
    cudaGetSymbolAddress((void**)&nrm,   g_nrm);
    cudaGetSymbolAddress((void**)&idx,   g_idx);
    cudaGetSymbolAddress((void**)&ycomb, g_ycomb);
    cudaGetSymbolAddress((void**)&poolI, g_poolI);
    cudaGetSymbolAddress((void**)&pts,   g_pts);
    cudaGetSymbolAddress((void**)&w1d,   g_w1d);
    cudaGetSymbolAddress((void**)&w1b,   g_w1b);
    cudaGetSymbolAddress((void**)&a3,    g_a3);
    cudaGetSymbolAddress((void**)&w3,    g_w3);

    cudaFuncSetAttribute(gramknn, cudaFuncAttributeMaxDynamicSharedMemorySize,
                         GK_SMEM_BYTES);
    cudaFuncSetAttribute(gramknn8, cudaFuncAttributeMaxDynamicSharedMemorySize,
                         GK_SMEM_BYTES);

    // lazy side-stream + events (created on first, uncaptured, call; reused after)
    static cudaStream_t sKnn = nullptr;
    static cudaEvent_t evFork[8], evJoin[8];
    if (!sKnn) {
        cudaStreamCreateWithFlags(&sKnn, cudaStreamNonBlocking);
        for (int i = 0; i < 8; i++) {
            cudaEventCreateWithFlags(&evFork[i], cudaEventDisableTiming);
            cudaEventCreateWithFlags(&evJoin[i], cudaEventDisableTiming);
        }
    }
    int ev = 0;

    const int BN = BN_TOT;   // 16384

    pad_pts<<<BN / 256, 256>>>(points, pts);
    pad_w1<<<1, 64>>>(W1, w1d, w1b);
    pool_init<<<(NB * 1024) / 256, 256>>>(poolI);

    // ---- front-loaded weight splits (no deps; overlap layer-1 knn) ----
    // L2: O=64, C=64, Kp=192
    split3_fast<<<(64 * 64 + 255) / 256, 256>>>(W2, 128, 6, w3 + OFF_L2, 0, 64 * 64);
    split3_fast<<<(64 * 64 + 255) / 256, 256>>>(W2 + 64, 128, 6,
                                                w3 + OFF_L2 + 64 * 192, 0, 64 * 64);
    // L3: O=128, C=64, Kp=192
    split3_fast<<<(128 * 64 + 255) / 256, 256>>>(W3, 128, 6, w3 + OFF_L3, 0, 128 * 64);
    split3_fast<<<(128 * 64 + 255) / 256, 256>>>(W3 + 64, 128, 6,
                                                 w3 + OFF_L3 + 128 * 192, 0, 128 * 64);
    // L4: O=256, C=128, Kp=384
    split3_fast<<<(256 * 128 + 255) / 256, 256>>>(W4, 256, 7, w3 + OFF_L4, 0, 256 * 128);
    split3_fast<<<(256 * 128 + 255) / 256, 256>>>(W4 + 128, 256, 7,
                                                  w3 + OFF_L4 + 256 * 384, 0, 256 * 128);
    // W5: O=1024, C=512, Kp=1536
    split3_fast<<<(1024 * 512) / 256, 256>>>(W5, 512, 9, w3 + OFF_W5, 0, 1024 * 512);
    // L1: O=64, C=4, Kp=32 (generic; after pad_w1)
    split3_w<<<(64 * 32 + 255) / 256, 256>>>(w1d, 4, 4, 32, w3 + OFF_L1, 0, 64 * 32);
    split3_w<<<(64 * 32 + 255) / 256, 256>>>(w1b, 4, 4, 32, w3 + OFF_L1, 64, 64 * 32);

    // fork-join edge layer: knn chain on sKnn, gemm chain on main (NULL) stream
    auto edge = [&](const float* feat, int lda, int C, int lg2C, int O,
                    const __nv_bfloat16* wsplit, int Kp,
                    const float* s, const float* t, int coff) {
        cudaEventRecord(evFork[ev], 0);
        cudaStreamWaitEvent(sKnn, evFork[ev], 0);
        rownorms<<<BN / 256, 256, 0, sKnn>>>(feat, lda, C, nrm);
        if (C >= 64)
            gramknn8<<<dim3(16, NB), 256, GK_SMEM_BYTES, sKnn>>>(feat, lda, C, nrm, idx);
        else
            gramknn<<<dim3(16, NB), 512, GK_SMEM_BYTES, sKnn>>>(feat, lda, C, nrm, idx);
        cudaEventRecord(evJoin[ev], sKnn);

        if (C >= 64) {
            split3_fast<<<(unsigned)(((long long)BN * C) / 256), 256>>>(
                feat, lda, lg2C, a3, 1, (long long)BN * C);
        } else {
            long long ta = (long long)BN * Kp;
            split3_feat<<<(unsigned)((ta + 255) / 256), 256>>>(feat, lda, C, Kp, a3, ta);
        }
        int N = 2 * O;
        hgemm<<<dim3(BN / 128, N / 128), 256>>>(a3, wsplit, ycomb, BN, N, Kp, N, nullptr);

        cudaStreamWaitEvent(0, evJoin[ev], 0);
        ev++;
        combine2<<<(BN * (O / 4)) / 256, 256>>>(ycomb, idx, s, t, xcat + coff, O);
    };

    edge(pts,        4,   4,   2,  64, w3 + OFF_L1, 32,  s1, t1, 0);
    edge(xcat + 0,   512, 64,  6,  64, w3 + OFF_L2, 192, s2, t2, 64);
    edge(xcat + 64,  512, 64,  6, 128, w3 + OFF_L3, 192, s3, t3, 128);
    edge(xcat + 128, 512, 128, 7, 256, w3 + OFF_L4, 384, s4, t4, 256);

    // point MLP with fused global max-pool (raw values; affine+lrelu in final_fc)
    {
        const int C = 512, O = 1024, Kp = 1536;
        split3_fast<<<(unsigned)(((long long)BN * C) / 256), 256>>>(
            xcat, 512, 9, a3, 1, (long long)BN * C);
        hgemm<<<dim3(BN / 128, O / 128), 256>>>(a3, w3 + OFF_W5, nullptr,
                                                BN, O, Kp, O, poolI);
    }
    final_fc<<<NB, 512>>>(poolI, s5, t5, Wf1, sf1, tf1, Wf2, bf2, sf2, tf2,
                          Wf3, bf3, (float*)d_out);
}

// round 12
// speedup vs baseline: 1.0156x; 1.0156x over previous
#include <cuda_runtime.h>
#include <cuda_bf16.h>
#include <stdint.h>

#define KNN 10
#define NPTS 2048
#define NB 8
#define BN_TOT (NB * NPTS)
#define LRELU(h) ((h) >= 0.f ? (h) : 0.2f * (h))

// ---------------- scratch (device globals; no runtime allocation) ----------------
__device__ float g_xcat[BN_TOT * 512];        // concat of out1..out4
__device__ float g_nrm[BN_TOT];
__device__ int   g_idx[BN_TOT * KNN];
__device__ float g_ycomb[BN_TOT * 512];       // [yd | yb] stacked cols (max 2*256)
__device__ int   g_poolI[NB * 1024];          // ordered-int max pool
__device__ float g_pts[BN_TOT * 4];
__device__ float g_w1d[64 * 4];
__device__ float g_w1b[64 * 4];
__device__ __nv_bfloat16 g_a3[BN_TOT * 1536]; // W5 activation split (incremental)
__device__ __nv_bfloat16 g_ag[BN_TOT * 384];  // per-layer GEMM activation split
__device__ __nv_bfloat16 g_w3[1024 * 1536];   // W5 weight split
__device__ __nv_bfloat16 g_wl[512 * 384];     // per-layer weight split (max 512x384)

// ---------------- packed f32x2 helpers ---------------------------------------------
__device__ __forceinline__ void ffma2(unsigned long long& d,
                                      unsigned long long a, unsigned long long b)
{
    asm("fma.rn.f32x2 %0, %1, %2, %0;" : "+l"(d) : "l"(a), "l"(b));
}
__device__ __forceinline__ unsigned long long dup2(float a)
{
    unsigned long long p;
    asm("mov.b64 %0, {%1, %1};" : "=l"(p) : "f"(a));
    return p;
}
__device__ __forceinline__ float2 unpk(unsigned long long p)
{
    float2 f;
    asm("mov.b64 {%0, %1}, %2;" : "=f"(f.x), "=f"(f.y) : "l"(p));
    return f;
}

// ---------------- ordered-int float max encoding ------------------------------------
__device__ __forceinline__ int f2ord(float f)
{
    int i = __float_as_int(f);
    return i >= 0 ? i : (i ^ 0x7fffffff);
}
__device__ __forceinline__ float ord2f(int i)
{
    return __int_as_float(i >= 0 ? i : (i ^ 0x7fffffff));
}

// ---------------- mma.sync helpers -------------------------------------------------
__device__ __forceinline__ uint32_t smem_u32(const void* p)
{
    uint32_t a;
    asm("{ .reg .u64 t; cvta.to.shared.u64 t, %1; cvt.u32.u64 %0, t; }"
        : "=r"(a) : "l"(p));
    return a;
}
__device__ __forceinline__ void ldm_x4(uint32_t& r0, uint32_t& r1,
                                       uint32_t& r2, uint32_t& r3, uint32_t addr)
{
    asm volatile("ldmatrix.sync.aligned.m8n8.x4.shared.b16 {%0,%1,%2,%3}, [%4];"
                 : "=r"(r0), "=r"(r1), "=r"(r2), "=r"(r3) : "r"(addr));
}
__device__ __forceinline__ void mma_bf16(float* d, const uint32_t* a, const uint32_t* b)
{
    asm volatile(
        "mma.sync.aligned.m16n8k16.row.col.f32.bf16.bf16.f32 "
        "{%0,%1,%2,%3}, {%4,%5,%6,%7}, {%8,%9}, {%0,%1,%2,%3};"
        : "+f"(d[0]), "+f"(d[1]), "+f"(d[2]), "+f"(d[3])
        : "r"(a[0]), "r"(a[1]), "r"(a[2]), "r"(a[3]), "r"(b[0]), "r"(b[1]));
}

// ================= HMMA bf16 NT GEMM, optional fused max-pool =====================
#define HS 40
__global__ __launch_bounds__(256) void hgemm(
    const __nv_bfloat16* __restrict__ A, const __nv_bfloat16* __restrict__ B,
    float* __restrict__ C, int M, int N, int Kp, int ldc, int* __restrict__ poolI)
{
    __shared__ __nv_bfloat16 As[2][128][HS];
    __shared__ __nv_bfloat16 Bs[2][128][HS];
    const int tid = threadIdx.x;
    const int wid = tid >> 5, lane = tid & 31;
    const int wm = wid >> 2, wn = wid & 3;
    const int m0 = blockIdx.x * 128, n0 = blockIdx.y * 128;

    const int lrow = tid >> 2, lkc = (tid & 3) * 8;

    float acc[4][4][4];
#pragma unroll
    for (int i = 0; i < 4; i++)
#pragma unroll
        for (int j = 0; j < 4; j++)
#pragma unroll
            for (int q = 0; q < 4; q++) acc[i][j][q] = 0.f;

    uint4 va0, va1, vb0, vb1;
    const __nv_bfloat16* arow0 = A + (long long)(m0 + lrow) * Kp + lkc;
    const __nv_bfloat16* arow1 = arow0 + (long long)64 * Kp;
    const __nv_bfloat16* brow0 = B + (long long)(n0 + lrow) * Kp + lkc;
    const __nv_bfloat16* brow1 = brow0 + (long long)64 * Kp;

    va0 = *(const uint4*)(arow0);
    va1 = *(const uint4*)(arow1);
    vb0 = *(const uint4*)(brow0);
    vb1 = *(const uint4*)(brow1);
    *(uint4*)(&As[0][lrow][lkc]) = va0;
    *(uint4*)(&As[0][lrow + 64][lkc]) = va1;
    *(uint4*)(&Bs[0][lrow][lkc]) = vb0;
    *(uint4*)(&Bs[0][lrow + 64][lkc]) = vb1;
    __syncthreads();

    const int nc = Kp >> 5;

    const int arow_f = wm * 64 + (lane & 15);
    const int ahalf = (lane >> 4) * 8;
    const int bgrp = lane >> 3;
    const int brow_base = wn * 32 + (lane & 7);
    const int bhalf = (bgrp & 1) * 8;

    for (int c = 0; c < nc; c++) {
        const int cur = c & 1;
        if (c + 1 < nc) {
            const int k1 = (c + 1) * 32;
            va0 = *(const uint4*)(arow0 + k1);
            va1 = *(const uint4*)(arow1 + k1);
            vb0 = *(const uint4*)(brow0 + k1);
            vb1 = *(const uint4*)(brow1 + k1);
        }
#pragma unroll
        for (int ks = 0; ks < 2; ks++) {
            uint32_t af[4][4], bf[4][2];
#pragma unroll
            for (int mt = 0; mt < 4; mt++) {
                uint32_t ad = smem_u32(&As[cur][arow_f + mt * 16][ks * 16 + ahalf]);
                ldm_x4(af[mt][0], af[mt][1], af[mt][2], af[mt][3], ad);
            }
#pragma unroll
            for (int p = 0; p < 2; p++) {
                int brow = brow_base + (p * 2 + (bgrp >> 1)) * 8;
                uint32_t bd = smem_u32(&Bs[cur][brow][ks * 16 + bhalf]);
                ldm_x4(bf[p * 2][0], bf[p * 2][1], bf[p * 2 + 1][0], bf[p * 2 + 1][1], bd);
            }
#pragma unroll
            for (int mt = 0; mt < 4; mt++)
#pragma unroll
                for (int nt = 0; nt < 4; nt++)
                    mma_bf16(acc[mt][nt], af[mt], bf[nt]);
        }
        __syncthreads();
        if (c + 1 < nc) {
            const int nxt = (c + 1) & 1;
            *(uint4*)(&As[nxt][lrow][lkc]) = va0;
            *(uint4*)(&As[nxt][lrow + 64][lkc]) = va1;
            *(uint4*)(&Bs[nxt][lrow][lkc]) = vb0;
            *(uint4*)(&Bs[nxt][lrow + 64][lkc]) = vb1;
            __syncthreads();
        }
    }

    if (poolI == nullptr) {
#pragma unroll
        for (int mt = 0; mt < 4; mt++) {
            int row = m0 + wm * 64 + mt * 16 + (lane >> 2);
#pragma unroll
            for (int nt = 0; nt < 4; nt++) {
                int col = n0 + wn * 32 + nt * 8 + (lane & 3) * 2;
                *(float2*)(C + (long long)row * ldc + col) =
                    make_float2(acc[mt][nt][0], acc[mt][nt][1]);
                *(float2*)(C + (long long)(row + 8) * ldc + col) =
                    make_float2(acc[mt][nt][2], acc[mt][nt][3]);
            }
        }
    } else {
        float cm[4][2];
#pragma unroll
        for (int nt = 0; nt < 4; nt++) {
            float c0 = -3.4e38f, c1 = -3.4e38f;
#pragma unroll
            for (int mt = 0; mt < 4; mt++) {
                c0 = fmaxf(c0, fmaxf(acc[mt][nt][0], acc[mt][nt][2]));
                c1 = fmaxf(c1, fmaxf(acc[mt][nt][1], acc[mt][nt][3]));
            }
            cm[nt][0] = c0; cm[nt][1] = c1;
        }
#pragma unroll
        for (int off = 4; off <= 16; off <<= 1)
#pragma unroll
            for (int nt = 0; nt < 4; nt++) {
                cm[nt][0] = fmaxf(cm[nt][0], __shfl_xor_sync(0xffffffffu, cm[nt][0], off));
                cm[nt][1] = fmaxf(cm[nt][1], __shfl_xor_sync(0xffffffffu, cm[nt][1], off));
            }
        if ((lane >> 2) == 0) {
            int* pb = poolI + (m0 >> 11) * 1024;
#pragma unroll
            for (int nt = 0; nt < 4; nt++) {
                int col = n0 + wn * 32 + nt * 8 + (lane & 3) * 2;
                atomicMax(pb + col, f2ord(cm[nt][0]));
                atomicMax(pb + col + 1, f2ord(cm[nt][1]));
            }
        }
    }
}

// ---------------- pool init ---------------------------------------------------------
__global__ void pool_init(int* __restrict__ poolI)
{
    poolI[blockIdx.x * blockDim.x + threadIdx.x] = 0x80000000;
}

// ---------------- splits ------------------------------------------------------------
__global__ void split3_feat(const float* __restrict__ src, int lda, int C, int Kp,
                            __nv_bfloat16* __restrict__ dst, long long total)
{
    long long g = (long long)blockIdx.x * blockDim.x + threadIdx.x;
    if (g >= total) return;
    int k = (int)(g % Kp);
    long long m = g / Kp;
    if (k < 3 * C) {
        int seg = k / C, c = k - seg * C;
        float x = src[m * lda + c];
        __nv_bfloat16 hi = __float2bfloat16(x);
        if (seg == 1) dst[g] = __float2bfloat16(x - __bfloat162float(hi));
        else dst[g] = hi;
        return;
    }
    dst[g] = __float2bfloat16(0.f);
}
__global__ void split3_w(const float* __restrict__ src, int lds, int C, int Kp,
                         __nv_bfloat16* __restrict__ dst, int rowoff, long long total)
{
    long long g = (long long)blockIdx.x * blockDim.x + threadIdx.x;
    if (g >= total) return;
    int k = (int)(g % Kp);
    long long o = g / Kp;
    __nv_bfloat16* d = dst + (rowoff + o) * (long long)Kp + k;
    if (k < 3 * C) {
        int seg = k / C, c = k - seg * C;
        float x = src[o * lds + c];
        __nv_bfloat16 hi = __float2bfloat16(x);
        if (seg == 2) *d = __float2bfloat16(x - __bfloat162float(hi));
        else *d = hi;
        return;
    }
    *d = __float2bfloat16(0.f);
}
__global__ void split3_fast(const float* __restrict__ src, int lds, int lg2C,
                            __nv_bfloat16* __restrict__ dst, int isA, long long total)
{
    long long g = (long long)blockIdx.x * blockDim.x + threadIdx.x;
    if (g >= total) return;
    const int C = 1 << lg2C;
    long long m = g >> lg2C;
    int c = (int)(g & (C - 1));
    float x = src[m * lds + c];
    __nv_bfloat16 hi = __float2bfloat16(x);
    __nv_bfloat16 lo = __float2bfloat16(x - __bfloat162float(hi));
    __nv_bfloat16* d = dst + m * (3LL << lg2C);
    d[c] = hi;
    d[C + c] = isA ? lo : hi;
    d[2 * C + c] = isA ? hi : lo;
}
// column-range [hi|lo|hi] split of xcat (stride 512) into a3 (stride 1536)
__global__ void split3_cols(const float* __restrict__ src, int c0, int ccount,
                            __nv_bfloat16* __restrict__ dst, long long total)
{
    long long g = (long long)blockIdx.x * blockDim.x + threadIdx.x;
    if (g >= total) return;
    long long m = g / ccount;
    int c = c0 + (int)(g - m * ccount);
    float x = src[m * 512 + c];
    __nv_bfloat16 hi = __float2bfloat16(x);
    __nv_bfloat16 lo = __float2bfloat16(x - __bfloat162float(hi));
    __nv_bfloat16* d = dst + m * 1536;
    d[c] = hi;
    d[512 + c] = lo;
    d[1024 + c] = hi;
}

// ================= fused gram + knn (R8/R9 proven 8x4 @ 512 threads) ==============
#define GK_SMEM_FLOATS (3 * 128 * 132)
#define GK_SMEM_BYTES (GK_SMEM_FLOATS * 4)
__global__ __launch_bounds__(512, 1) void gramknn(
    const float* __restrict__ feat, int lda, int K,
    const float* __restrict__ nrm, int* __restrict__ idxout)
{
    extern __shared__ float sm[];
    float (*As)[132]    = reinterpret_cast<float(*)[132]>(sm);
    float (*Bs)[132]    = reinterpret_cast<float(*)[132]>(sm + 128 * 132);
    float (*stage)[132] = reinterpret_cast<float(*)[132]>(sm + 2 * 128 * 132);

    const int strip = blockIdx.x;
    const int b = blockIdx.y;
    const int i0 = strip * 128;
    const float* fb = feat + (long long)b * NPTS * lda;
    const float* nb = nrm + b * NPTS;
    const int tid = threadIdx.x;

    for (int e = tid; e < K * 128; e += 512) {
        int k = e >> 7, m = e & 127;
        As[k][m] = fb[(long long)(i0 + m) * lda + k];
    }

    const int cg = tid & 31;
    const int rg = tid >> 5;
    const int srow = tid & 127;
    const int sq = tid >> 7;
    const int self = i0 + srow;
    const int Kq = K >> 2;

    float bd[KNN];
    int bj[KNN];
#pragma unroll
    for (int p = 0; p < KNN; p++) { bd[p] = 3.4e38f; bj[p] = 0x7fffffff; }

    for (int jt = 0; jt < 16; jt++) {
        const int j0 = jt * 128;

        for (int e = tid; e < 128 * Kq; e += 512) {
            int j = e / Kq;
            int kq = (e - j * Kq) * 4;
            float4 v = *(const float4*)(fb + (long long)(j0 + j) * lda + kq);
            Bs[kq + 0][j] = v.x; Bs[kq + 1][j] = v.y;
            Bs[kq + 2][j] = v.z; Bs[kq + 3][j] = v.w;
        }
        __syncthreads();

        unsigned long long acc[8][2];
#pragma unroll
        for (int r = 0; r < 8; r++) { acc[r][0] = 0ull; acc[r][1] = 0ull; }

#pragma unroll 8
        for (int kk = 0; kk < K; kk++) {
            float4 a0 = *(const float4*)(&As[kk][rg * 8]);
            float4 a1 = *(const float4*)(&As[kk][rg * 8 + 4]);
            ulonglong2 bb = *(const ulonglong2*)(&Bs[kk][cg * 4]);
            unsigned long long pa;
            pa = dup2(a0.x); ffma2(acc[0][0], pa, bb.x); ffma2(acc[0][1], pa, bb.y);
            pa = dup2(a0.y); ffma2(acc[1][0], pa, bb.x); ffma2(acc[1][1], pa, bb.y);
            pa = dup2(a0.z); ffma2(acc[2][0], pa, bb.x); ffma2(acc[2][1], pa, bb.y);
            pa = dup2(a0.w); ffma2(acc[3][0], pa, bb.x); ffma2(acc[3][1], pa, bb.y);
            pa = dup2(a1.x); ffma2(acc[4][0], pa, bb.x); ffma2(acc[4][1], pa, bb.y);
            pa = dup2(a1.y); ffma2(acc[5][0], pa, bb.x); ffma2(acc[5][1], pa, bb.y);
            pa = dup2(a1.z); ffma2(acc[6][0], pa, bb.x); ffma2(acc[6][1], pa, bb.y);
            pa = dup2(a1.w); ffma2(acc[7][0], pa, bb.x); ffma2(acc[7][1], pa, bb.y);
        }

        float4 nj = *(const float4*)(nb + j0 + cg * 4);
#pragma unroll
        for (int r = 0; r < 8; r++) {
            float2 lo = unpk(acc[r][0]);
            float2 hi = unpk(acc[r][1]);
            float4 dv;
            dv.x = fmaf(-2.f, lo.x, nj.x);
            dv.y = fmaf(-2.f, lo.y, nj.y);
            dv.z = fmaf(-2.f, hi.x, nj.z);
            dv.w = fmaf(-2.f, hi.y, nj.w);
            *(float4*)(&stage[rg * 8 + r][cg * 4]) = dv;
        }
        __syncthreads();

#pragma unroll
        for (int q = 0; q < 8; q++) {
            int c4 = sq * 32 + q * 4;
            float4 v = *(const float4*)(&stage[srow][c4]);
            float m4 = fminf(fminf(v.x, v.y), fminf(v.z, v.w));
            if (m4 < bd[KNN - 1]) {
                float dv4[4] = {v.x, v.y, v.z, v.w};
#pragma unroll
                for (int e = 0; e < 4; e++) {
                    int j = j0 + c4 + e;
                    float d = dv4[e];
                    if (j != self && d < bd[KNN - 1]) {
                        bd[KNN - 1] = d; bj[KNN - 1] = j;
#pragma unroll
                        for (int p = KNN - 1; p > 0; p--) {
                            if (bd[p] < bd[p - 1]) {
                                float td = bd[p]; bd[p] = bd[p - 1]; bd[p - 1] = td;
                                int tj = bj[p]; bj[p] = bj[p - 1]; bj[p - 1] = tj;
                            }
                        }
                    }
                }
            }
        }
    }
    __syncthreads();

    float* mb = sm;
    {
        int base = (srow * 4 + sq) * 24;
#pragma unroll
        for (int p = 0; p < KNN; p++) {
            mb[base + p] = bd[p];
            ((int*)mb)[base + 12 + p] = bj[p];
        }
        mb[base + KNN] = 3.4e38f;
        ((int*)mb)[base + 12 + KNN] = 0x7fffffff;
    }
    __syncthreads();

    if (tid < 128) {
        int row = tid;
        int ptr[4] = {0, 0, 0, 0};
        int* outp = idxout + ((long long)(b * NPTS + i0 + row)) * KNN;
#pragma unroll
        for (int q = 0; q < KNN; q++) {
            float bestd = 3.4e38f; int bestj = 0x7fffffff; int bl = 0;
#pragma unroll
            for (int l = 0; l < 4; l++) {
                int base = (row * 4 + l) * 24;
                float dl = mb[base + ptr[l]];
                int jl = ((int*)mb)[base + 12 + ptr[l]];
                if (dl < bestd || (dl == bestd && jl < bestj)) {
                    bestd = dl; bestj = jl; bl = l;
                }
            }
            outp[q] = bestj;
            ptr[bl]++;
        }
    }
}

// ---------------- row squared norms ------------------------------------------------
__global__ void rownorms(const float* __restrict__ feat, int lda, int C,
                         float* __restrict__ nrm)
{
    int g = blockIdx.x * blockDim.x + threadIdx.x;
    const float* p = feat + (long long)g * lda;
    float s = 0.f;
    for (int c = 0; c < C; c += 4) {
        float4 v = *(const float4*)(p + c);
        s += v.x * v.x + v.y * v.y + v.z * v.z + v.w * v.w;
    }
    nrm[g] = s;
}

// ---------------- combine (float4) --------------------------------------------------
__global__ void combine2(const float* __restrict__ ycomb,
                         const int* __restrict__ idx, const float* __restrict__ s,
                         const float* __restrict__ t, float* __restrict__ outx, int O)
{
    int g = blockIdx.x * blockDim.x + threadIdx.x;
    int q = O >> 2;
    int bn = g / q;
    int o = (g - bn * q) << 2;
    const int* ip = idx + (long long)bn * KNN;
    int base = bn & ~2047;
    const int ld = 2 * O;
    float4 m = make_float4(-3.4e38f, -3.4e38f, -3.4e38f, -3.4e38f);
#pragma unroll
    for (int k = 0; k < KNN; k++) {
        int j = ip[k];
        float4 v = *(const float4*)(ycomb + (long long)(base + j) * ld + o);
        m.x = fmaxf(m.x, v.x); m.y = fmaxf(m.y, v.y);
        m.z = fmaxf(m.z, v.z); m.w = fmaxf(m.w, v.w);
    }
    float4 ydv = *(const float4*)(ycomb + (long long)bn * ld + o);
    float4 ybv = *(const float4*)(ycomb + (long long)bn * ld + O + o);
    float4 sv = *(const float4*)(s + o);
    float4 tv = *(const float4*)(t + o);
    float4 h;
    h.x = (m.x - ydv.x + ybv.x) * sv.x + tv.x;
    h.y = (m.y - ydv.y + ybv.y) * sv.y + tv.y;
    h.z = (m.z - ydv.z + ybv.z) * sv.z + tv.z;
    h.w = (m.w - ydv.w + ybv.w) * sv.w + tv.w;
    h.x = LRELU(h.x); h.y = LRELU(h.y); h.z = LRELU(h.z); h.w = LRELU(h.w);
    *(float4*)(outx + (long long)bn * 512 + o) = h;
}

// ---------------- input padding helpers -------------------------------------------
__global__ void pad_pts(const float* __restrict__ p, float* __restrict__ pp)
{
    int g = blockIdx.x * blockDim.x + threadIdx.x;
    pp[g * 4 + 0] = p[g * 3 + 0];
    pp[g * 4 + 1] = p[g * 3 + 1];
    pp[g * 4 + 2] = p[g * 3 + 2];
    pp[g * 4 + 3] = 0.f;
}
__global__ void pad_w1(const float* __restrict__ W1, float* __restrict__ wd,
                       float* __restrict__ wb)
{
    int o = threadIdx.x;
#pragma unroll
    for (int c = 0; c < 3; c++) {
        wd[o * 4 + c] = W1[o * 6 + c];
        wb[o * 4 + c] = W1[o * 6 + 3 + c];
    }
    wd[o * 4 + 3] = 0.f;
    wb[o * 4 + 3] = 0.f;
}

// ---------------- final 3 FC layers, fused (reads ordered-int pool) ----------------
__global__ void final_fc(const int* __restrict__ poolI,
                         const float* __restrict__ s5, const float* __restrict__ t5,
                         const float* __restrict__ Wf1, const float* __restrict__ sf1,
                         const float* __restrict__ tf1,
                         const float* __restrict__ Wf2, const float* __restrict__ bf2,
                         const float* __restrict__ sf2, const float* __restrict__ tf2,
                         const float* __restrict__ Wf3, const float* __restrict__ bf3,
                         float* __restrict__ out)
{
    __shared__ float sx[1024];
    __shared__ float h1[512];
    __shared__ float h2[256];
    int b = blockIdx.x, tid = threadIdx.x;
    {
        float v0 = ord2f(poolI[b * 1024 + tid]) * s5[tid] + t5[tid];
        float v1 = ord2f(poolI[b * 1024 + tid + 512]) * s5[tid + 512] + t5[tid + 512];
        sx[tid] = LRELU(v0);
        sx[tid + 512] = LRELU(v1);
    }
    __syncthreads();
    {
        const float* w = Wf1 + (long long)tid * 1024;
        float a0 = 0.f, a1 = 0.f, a2 = 0.f, a3 = 0.f;
        for (int c = 0; c < 1024; c += 4) {
            a0 = fmaf(w[c + 0], sx[c + 0], a0);
            a1 = fmaf(w[c + 1], sx[c + 1], a1);
            a2 = fmaf(w[c + 2], sx[c + 2], a2);
            a3 = fmaf(w[c + 3], sx[c + 3], a3);
        }
        float h = ((a0 + a1) + (a2 + a3)) * sf1[tid] + tf1[tid];
        h1[tid] = LRELU(h);
    }
    __syncthreads();
    if (tid < 256) {
        const float* w = Wf2 + (long long)tid * 512;
        float a0 = 0.f, a1 = 0.f, a2 = 0.f, a3 = 0.f;
        for (int c = 0; c < 512; c += 4) {
            a0 = fmaf(w[c + 0], h1[c + 0], a0);
            a1 = fmaf(w[c + 1], h1[c + 1], a1);
            a2 = fmaf(w[c + 2], h1[c + 2], a2);
            a3 = fmaf(w[c + 3], h1[c + 3], a3);
        }
        float h = (((a0 + a1) + (a2 + a3)) + bf2[tid]) * sf2[tid] + tf2[tid];
        h2[tid] = LRELU(h);
    }
    __syncthreads();
    if (tid < 3) {
        const float* w = Wf3 + (long long)tid * 256;
        float a = 0.f;
        for (int c = 0; c < 256; c++) a = fmaf(w[c], h2[c], a);
        out[b * 3 + tid] = a + bf3[tid];
    }
}

// ------------------------------- host side ---------------------------------------
extern "C" void kernel_launch(void* const* d_in, const int* in_sizes, int n_in,
                              void* d_out, int out_size)
{
    const float* points = (const float*)d_in[0];
    const float* W1 = (const float*)d_in[1];  const float* s1 = (const float*)d_in[2];  const float* t1 = (const float*)d_in[3];
    const float* W2 = (const float*)d_in[4];  const float* s2 = (const float*)d_in[5];  const float* t2 = (const float*)d_in[6];
    const float* W3 = (const float*)d_in[7];  const float* s3 = (const float*)d_in[8];  const float* t3 = (const float*)d_in[9];
    const float* W4 = (const float*)d_in[10]; const float* s4 = (const float*)d_in[11]; const float* t4 = (const float*)d_in[12];
    const float* W5 = (const float*)d_in[13]; const float* s5 = (const float*)d_in[14]; const float* t5 = (const float*)d_in[15];
    const float* Wf1 = (const float*)d_in[16]; const float* sf1 = (const float*)d_in[17]; const float* tf1 = (const float*)d_in[18];
    const float* Wf2 = (const float*)d_in[19]; const float* bf2 = (const float*)d_in[20];
    const float* sf2 = (const float*)d_in[21]; const float* tf2 = (const float*)d_in[22];
    const float* Wf3 = (const float*)d_in[23]; const float* bf3 = (const float*)d_in[24];

    float *xcat, *nrm, *ycomb, *pts, *w1d, *w1b;
    int *idx, *poolI;
    __nv_bfloat16 *a3, *ag, *w3, *wl;
    cudaGetSymbolAddress((void**)&xcat,  g_xcat);
    cudaGetSymbolAddress((void**)&nrm,   g_nrm);
    cudaGetSymbolAddress((void**)&idx,   g_idx);
    cudaGetSymbolAddress((void**)&ycomb, g_ycomb);
    cudaGetSymbolAddress((void**)&poolI, g_poolI);
    cudaGetSymbolAddress((void**)&pts,   g_pts);
    cudaGetSymbolAddress((void**)&w1d,   g_w1d);
    cudaGetSymbolAddress((void**)&w1b,   g_w1b);
    cudaGetSymbolAddress((void**)&a3,    g_a3);
    cudaGetSymbolAddress((void**)&ag,    g_ag);
    cudaGetSymbolAddress((void**)&w3,    g_w3);
    cudaGetSymbolAddress((void**)&wl,    g_wl);

    cudaFuncSetAttribute(gramknn, cudaFuncAttributeMaxDynamicSharedMemorySize,
                         GK_SMEM_BYTES);

    static cudaStream_t sKnn = nullptr;
    static cudaEvent_t evFork[8], evJoin[8];
    if (!sKnn) {
        cudaStreamCreateWithFlags(&sKnn, cudaStreamNonBlocking);
        for (int i = 0; i < 8; i++) {
            cudaEventCreateWithFlags(&evFork[i], cudaEventDisableTiming);
            cudaEventCreateWithFlags(&evJoin[i], cudaEventDisableTiming);
        }
    }
    int ev = 0;

    const int BN = BN_TOT;   // 16384

    pad_pts<<<BN / 256, 256>>>(points, pts);
    pad_w1<<<1, 64>>>(W1, w1d, w1b);
    pool_init<<<(NB * 1024) / 256, 256>>>(poolI);
    // W5 weight split: no deps -> hoisted to start (overlaps layer-1 knn)
    split3_fast<<<(1024 * 512) / 256, 256>>>(W5, 512, 9, w3, 0, 1024LL * 512);

    auto lg2 = [](int c) { int l = 0; while ((1 << l) < c) l++; return l; };

    // fork-join edge layer; after combine2, split finished xcat slice into a3
    auto edge = [&](const float* feat, int lda, int C, int O,
                    const float* Wd, const float* Wb, int ldw,
                    const float* s, const float* t, int coff, int ccount) {
        cudaEventRecord(evFork[ev], 0);
        cudaStreamWaitEvent(sKnn, evFork[ev], 0);
        rownorms<<<BN / 256, 256, 0, sKnn>>>(feat, lda, C, nrm);
        gramknn<<<dim3(16, NB), 512, GK_SMEM_BYTES, sKnn>>>(feat, lda, C, nrm, idx);
        cudaEventRecord(evJoin[ev], sKnn);

        int Kp;
        if (C >= 64) {
            Kp = 3 * C;
            int l = lg2(C);
            split3_fast<<<(unsigned)(((long long)BN * C) / 256), 256>>>(
                feat, lda, l, ag, 1, (long long)BN * C);
            split3_fast<<<(unsigned)(((long long)O * C + 255) / 256), 256>>>(
                Wd, ldw, l, wl, 0, (long long)O * C);
            split3_fast<<<(unsigned)(((long long)O * C + 255) / 256), 256>>>(
                Wb, ldw, l, wl + (long long)O * Kp, 0, (long long)O * C);
        } else {
            Kp = 32;
            long long ta = (long long)BN * Kp;
            split3_feat<<<(unsigned)((ta + 255) / 256), 256>>>(feat, lda, C, Kp, ag, ta);
            long long tw = (long long)O * Kp;
            split3_w<<<(unsigned)((tw + 255) / 256), 256>>>(Wd, ldw, C, Kp, wl, 0, tw);
            split3_w<<<(unsigned)((tw + 255) / 256), 256>>>(Wb, ldw, C, Kp, wl, O, tw);
        }
        int N = 2 * O;
        hgemm<<<dim3(BN / 128, N / 128), 256>>>(ag, wl, ycomb, BN, N, Kp, N, nullptr);

        cudaStreamWaitEvent(0, evJoin[ev], 0);
        ev++;
        combine2<<<(BN * (O / 4)) / 256, 256>>>(ycomb, idx, s, t, xcat + coff, O);
        // incremental W5 activation split for this finished slice
        long long tn = (long long)BN * ccount;
        split3_cols<<<(unsigned)((tn + 255) / 256), 256>>>(xcat, coff, ccount, a3, tn);
    };

    edge(pts,        4,   4,   64, w1d, w1b,      4,   s1, t1, 0,   64);
    edge(xcat + 0,   512, 64,  64, W2,  W2 + 64,  128, s2, t2, 64,  64);
    edge(xcat + 64,  512, 64,  128, W3, W3 + 64,  128, s3, t3, 128, 128);
    edge(xcat + 128, 512, 128, 256, W4, W4 + 128, 256, s4, t4, 256, 256);

    // point MLP with fused global max-pool (a3 assembled incrementally above)
    hgemm<<<dim3(BN / 128, 1024 / 128), 256>>>(a3, w3, nullptr, BN, 1024, 1536,
                                               1024, poolI);
    final_fc<<<NB, 512>>>(poolI, s5, t5, Wf1, sf1, tf1, Wf2, bf2, sf2, tf2,
                          Wf3, bf3, (float*)d_out);
}

// round 13
// speedup vs baseline: 1.0644x; 1.0480x over previous
#include <cuda_runtime.h>
#include <cuda_bf16.h>
#include <stdint.h>

#define KNN 10
#define NPTS 2048
#define NB 8
#define BN_TOT (NB * NPTS)
#define LRELU(h) ((h) >= 0.f ? (h) : 0.2f * (h))

// ---------------- scratch (device globals; no runtime allocation) ----------------
__device__ float g_xcat[BN_TOT * 512];        // concat of out1..out4
__device__ float g_nrm[BN_TOT];
__device__ int   g_idx[BN_TOT * KNN];
__device__ float g_ycomb[BN_TOT * 512];       // [yd | yb] stacked cols (max 2*256)
__device__ int   g_poolI[NB * 1024];          // ordered-int max pool
__device__ float g_pts[BN_TOT * 4];
__device__ float g_w1d[64 * 4];
__device__ float g_w1b[64 * 4];
__device__ __nv_bfloat16 g_a3[BN_TOT * 1536]; // W5 activation split
__device__ __nv_bfloat16 g_ag[BN_TOT * 384];  // per-layer GEMM activation split
__device__ __nv_bfloat16 g_w3[1024 * 1536];   // W5 weight split
__device__ __nv_bfloat16 g_wl[512 * 384];     // per-layer weight split (max 512x384)

// ---------------- packed f32x2 helpers ---------------------------------------------
__device__ __forceinline__ void ffma2(unsigned long long& d,
                                      unsigned long long a, unsigned long long b)
{
    asm("fma.rn.f32x2 %0, %1, %2, %0;" : "+l"(d) : "l"(a), "l"(b));
}
__device__ __forceinline__ unsigned long long dup2(float a)
{
    unsigned long long p;
    asm("mov.b64 %0, {%1, %1};" : "=l"(p) : "f"(a));
    return p;
}
__device__ __forceinline__ float2 unpk(unsigned long long p)
{
    float2 f;
    asm("mov.b64 {%0, %1}, %2;" : "=f"(f.x), "=f"(f.y) : "l"(p));
    return f;
}

// ---------------- ordered-int float max encoding ------------------------------------
__device__ __forceinline__ int f2ord(float f)
{
    int i = __float_as_int(f);
    return i >= 0 ? i : (i ^ 0x7fffffff);
}
__device__ __forceinline__ float ord2f(int i)
{
    return __int_as_float(i >= 0 ? i : (i ^ 0x7fffffff));
}

// ---------------- mma.sync / cp.async helpers ---------------------------------------
__device__ __forceinline__ uint32_t smem_u32(const void* p)
{
    uint32_t a;
    asm("{ .reg .u64 t; cvta.to.shared.u64 t, %1; cvt.u32.u64 %0, t; }"
        : "=r"(a) : "l"(p));
    return a;
}
__device__ __forceinline__ void ldm_x4(uint32_t& r0, uint32_t& r1,
                                       uint32_t& r2, uint32_t& r3, uint32_t addr)
{
    asm volatile("ldmatrix.sync.aligned.m8n8.x4.shared.b16 {%0,%1,%2,%3}, [%4];"
                 : "=r"(r0), "=r"(r1), "=r"(r2), "=r"(r3) : "r"(addr));
}
__device__ __forceinline__ void mma_bf16(float* d, const uint32_t* a, const uint32_t* b)
{
    asm volatile(
        "mma.sync.aligned.m16n8k16.row.col.f32.bf16.bf16.f32 "
        "{%0,%1,%2,%3}, {%4,%5,%6,%7}, {%8,%9}, {%0,%1,%2,%3};"
        : "+f"(d[0]), "+f"(d[1]), "+f"(d[2]), "+f"(d[3])
        : "r"(a[0]), "r"(a[1]), "r"(a[2]), "r"(a[3]), "r"(b[0]), "r"(b[1]));
}
__device__ __forceinline__ void cp16(void* smem, const void* g)
{
    uint32_t s = smem_u32(smem);
    asm volatile("cp.async.cg.shared.global [%0], [%1], 16;" :: "r"(s), "l"(g));
}
#define CP_COMMIT() asm volatile("cp.async.commit_group;" ::: "memory")
#define CP_WAIT(N)  asm volatile("cp.async.wait_group %0;" :: "n"(N) : "memory")

// ================= HMMA bf16 NT GEMM: 3-stage cp.async pipeline ===================
// C[m][n] = sum_k A[m][k]*B[n][k]. One barrier per 32-k chunk; loads 2 chunks ahead.
// If poolI != null: skip C, atomically max-reduce per (batch, col) into poolI.
#define HS 40
#define STG 3
__global__ __launch_bounds__(256) void hgemm(
    const __nv_bfloat16* __restrict__ A, const __nv_bfloat16* __restrict__ B,
    float* __restrict__ C, int M, int N, int Kp, int ldc, int* __restrict__ poolI)
{
    __shared__ __nv_bfloat16 As[STG][128][HS];
    __shared__ __nv_bfloat16 Bs[STG][128][HS];
    const int tid = threadIdx.x;
    const int wid = tid >> 5, lane = tid & 31;
    const int wm = wid >> 2, wn = wid & 3;
    const int m0 = blockIdx.x * 128, n0 = blockIdx.y * 128;

    const int lrow = tid >> 2, lkc = (tid & 3) * 8;

    float acc[4][4][4];
#pragma unroll
    for (int i = 0; i < 4; i++)
#pragma unroll
        for (int j = 0; j < 4; j++)
#pragma unroll
            for (int q = 0; q < 4; q++) acc[i][j][q] = 0.f;

    const __nv_bfloat16* arow0 = A + (long long)(m0 + lrow) * Kp + lkc;
    const __nv_bfloat16* arow1 = arow0 + (long long)64 * Kp;
    const __nv_bfloat16* brow0 = B + (long long)(n0 + lrow) * Kp + lkc;
    const __nv_bfloat16* brow1 = brow0 + (long long)64 * Kp;

    const int nc = Kp >> 5;

    // prologue: issue stages 0..STG-2
#pragma unroll
    for (int s = 0; s < STG - 1; s++) {
        if (s < nc) {
            const int k = s * 32;
            cp16(&As[s][lrow][lkc], arow0 + k);
            cp16(&As[s][lrow + 64][lkc], arow1 + k);
            cp16(&Bs[s][lrow][lkc], brow0 + k);
            cp16(&Bs[s][lrow + 64][lkc], brow1 + k);
        }
        CP_COMMIT();
    }
    CP_WAIT(STG - 2);
    __syncthreads();   // stage 0 ready

    const int arow_f = wm * 64 + (lane & 15);
    const int ahalf = (lane >> 4) * 8;
    const int bgrp = lane >> 3;
    const int brow_base = wn * 32 + (lane & 7);
    const int bhalf = (bgrp & 1) * 8;

    for (int c = 0; c < nc; c++) {
        const int cur = c % STG;
        // issue loads 2 chunks ahead (writes stage (c-1)%STG: readers done last iter)
        if (c + STG - 1 < nc) {
            const int s = (c + STG - 1) % STG;
            const int k = (c + STG - 1) * 32;
            cp16(&As[s][lrow][lkc], arow0 + k);
            cp16(&As[s][lrow + 64][lkc], arow1 + k);
            cp16(&Bs[s][lrow][lkc], brow0 + k);
            cp16(&Bs[s][lrow + 64][lkc], brow1 + k);
        }
        CP_COMMIT();
#pragma unroll
        for (int ks = 0; ks < 2; ks++) {
            uint32_t af[4][4], bf[4][2];
#pragma unroll
            for (int mt = 0; mt < 4; mt++) {
                uint32_t ad = smem_u32(&As[cur][arow_f + mt * 16][ks * 16 + ahalf]);
                ldm_x4(af[mt][0], af[mt][1], af[mt][2], af[mt][3], ad);
            }
#pragma unroll
            for (int p = 0; p < 2; p++) {
                int brow = brow_base + (p * 2 + (bgrp >> 1)) * 8;
                uint32_t bd = smem_u32(&Bs[cur][brow][ks * 16 + bhalf]);
                ldm_x4(bf[p * 2][0], bf[p * 2][1], bf[p * 2 + 1][0], bf[p * 2 + 1][1], bd);
            }
#pragma unroll
            for (int mt = 0; mt < 4; mt++)
#pragma unroll
                for (int nt = 0; nt < 4; nt++)
                    mma_bf16(acc[mt][nt], af[mt], bf[nt]);
        }
        CP_WAIT(STG - 2);   // next stage's data arrived
        __syncthreads();    // all warps done reading stage cur
    }

    if (poolI == nullptr) {
#pragma unroll
        for (int mt = 0; mt < 4; mt++) {
            int row = m0 + wm * 64 + mt * 16 + (lane >> 2);
#pragma unroll
            for (int nt = 0; nt < 4; nt++) {
                int col = n0 + wn * 32 + nt * 8 + (lane & 3) * 2;
                *(float2*)(C + (long long)row * ldc + col) =
                    make_float2(acc[mt][nt][0], acc[mt][nt][1]);
                *(float2*)(C + (long long)(row + 8) * ldc + col) =
                    make_float2(acc[mt][nt][2], acc[mt][nt][3]);
            }
        }
    } else {
        float cm[4][2];
#pragma unroll
        for (int nt = 0; nt < 4; nt++) {
            float c0 = -3.4e38f, c1 = -3.4e38f;
#pragma unroll
            for (int mt = 0; mt < 4; mt++) {
                c0 = fmaxf(c0, fmaxf(acc[mt][nt][0], acc[mt][nt][2]));
                c1 = fmaxf(c1, fmaxf(acc[mt][nt][1], acc[mt][nt][3]));
            }
            cm[nt][0] = c0; cm[nt][1] = c1;
        }
#pragma unroll
        for (int off = 4; off <= 16; off <<= 1)
#pragma unroll
            for (int nt = 0; nt < 4; nt++) {
                cm[nt][0] = fmaxf(cm[nt][0], __shfl_xor_sync(0xffffffffu, cm[nt][0], off));
                cm[nt][1] = fmaxf(cm[nt][1], __shfl_xor_sync(0xffffffffu, cm[nt][1], off));
            }
        if ((lane >> 2) == 0) {
            int* pb = poolI + (m0 >> 11) * 1024;
#pragma unroll
            for (int nt = 0; nt < 4; nt++) {
                int col = n0 + wn * 32 + nt * 8 + (lane & 3) * 2;
                atomicMax(pb + col, f2ord(cm[nt][0]));
                atomicMax(pb + col + 1, f2ord(cm[nt][1]));
            }
        }
    }
}

// ---------------- pool init ---------------------------------------------------------
__global__ void pool_init(int* __restrict__ poolI)
{
    poolI[blockIdx.x * blockDim.x + threadIdx.x] = 0x80000000;
}

// ---------------- splits ------------------------------------------------------------
__global__ void split3_feat(const float* __restrict__ src, int lda, int C, int Kp,
                            __nv_bfloat16* __restrict__ dst, long long total)
{
    long long g = (long long)blockIdx.x * blockDim.x + threadIdx.x;
    if (g >= total) return;
    int k = (int)(g % Kp);
    long long m = g / Kp;
    if (k < 3 * C) {
        int seg = k / C, c = k - seg * C;
        float x = src[m * lda + c];
        __nv_bfloat16 hi = __float2bfloat16(x);
        if (seg == 1) dst[g] = __float2bfloat16(x - __bfloat162float(hi));
        else dst[g] = hi;
        return;
    }
    dst[g] = __float2bfloat16(0.f);
}
__global__ void split3_w(const float* __restrict__ src, int lds, int C, int Kp,
                         __nv_bfloat16* __restrict__ dst, int rowoff, long long total)
{
    long long g = (long long)blockIdx.x * blockDim.x + threadIdx.x;
    if (g >= total) return;
    int k = (int)(g % Kp);
    long long o = g / Kp;
    __nv_bfloat16* d = dst + (rowoff + o) * (long long)Kp + k;
    if (k < 3 * C) {
        int seg = k / C, c = k - seg * C;
        float x = src[o * lds + c];
        __nv_bfloat16 hi = __float2bfloat16(x);
        if (seg == 2) *d = __float2bfloat16(x - __bfloat162float(hi));
        else *d = hi;
        return;
    }
    *d = __float2bfloat16(0.f);
}
__global__ void split3_fast(const float* __restrict__ src, int lds, int lg2C,
                            __nv_bfloat16* __restrict__ dst, int isA, long long total)
{
    long long g = (long long)blockIdx.x * blockDim.x + threadIdx.x;
    if (g >= total) return;
    const int C = 1 << lg2C;
    long long m = g >> lg2C;
    int c = (int)(g & (C - 1));
    float x = src[m * lds + c];
    __nv_bfloat16 hi = __float2bfloat16(x);
    __nv_bfloat16 lo = __float2bfloat16(x - __bfloat162float(hi));
    __nv_bfloat16* d = dst + m * (3LL << lg2C);
    d[c] = hi;
    d[C + c] = isA ? lo : hi;
    d[2 * C + c] = isA ? hi : lo;
}

// ================= fused gram + knn (R8/R9 proven 8x4 @ 512 threads) ==============
#define GK_SMEM_FLOATS (3 * 128 * 132)
#define GK_SMEM_BYTES (GK_SMEM_FLOATS * 4)
__global__ __launch_bounds__(512, 1) void gramknn(
    const float* __restrict__ feat, int lda, int K,
    const float* __restrict__ nrm, int* __restrict__ idxout)
{
    extern __shared__ float sm[];
    float (*As)[132]    = reinterpret_cast<float(*)[132]>(sm);
    float (*Bs)[132]    = reinterpret_cast<float(*)[132]>(sm + 128 * 132);
    float (*stage)[132] = reinterpret_cast<float(*)[132]>(sm + 2 * 128 * 132);

    const int strip = blockIdx.x;
    const int b = blockIdx.y;
    const int i0 = strip * 128;
    const float* fb = feat + (long long)b * NPTS * lda;
    const float* nb = nrm + b * NPTS;
    const int tid = threadIdx.x;

    for (int e = tid; e < K * 128; e += 512) {
        int k = e >> 7, m = e & 127;
        As[k][m] = fb[(long long)(i0 + m) * lda + k];
    }

    const int cg = tid & 31;
    const int rg = tid >> 5;
    const int srow = tid & 127;
    const int sq = tid >> 7;
    const int self = i0 + srow;
    const int Kq = K >> 2;

    float bd[KNN];
    int bj[KNN];
#pragma unroll
    for (int p = 0; p < KNN; p++) { bd[p] = 3.4e38f; bj[p] = 0x7fffffff; }

    for (int jt = 0; jt < 16; jt++) {
        const int j0 = jt * 128;

        for (int e = tid; e < 128 * Kq; e += 512) {
            int j = e / Kq;
            int kq = (e - j * Kq) * 4;
            float4 v = *(const float4*)(fb + (long long)(j0 + j) * lda + kq);
            Bs[kq + 0][j] = v.x; Bs[kq + 1][j] = v.y;
            Bs[kq + 2][j] = v.z; Bs[kq + 3][j] = v.w;
        }
        __syncthreads();

        unsigned long long acc[8][2];
#pragma unroll
        for (int r = 0; r < 8; r++) { acc[r][0] = 0ull; acc[r][1] = 0ull; }

#pragma unroll 8
        for (int kk = 0; kk < K; kk++) {
            float4 a0 = *(const float4*)(&As[kk][rg * 8]);
            float4 a1 = *(const float4*)(&As[kk][rg * 8 + 4]);
            ulonglong2 bb = *(const ulonglong2*)(&Bs[kk][cg * 4]);
            unsigned long long pa;
            pa = dup2(a0.x); ffma2(acc[0][0], pa, bb.x); ffma2(acc[0][1], pa, bb.y);
            pa = dup2(a0.y); ffma2(acc[1][0], pa, bb.x); ffma2(acc[1][1], pa, bb.y);
            pa = dup2(a0.z); ffma2(acc[2][0], pa, bb.x); ffma2(acc[2][1], pa, bb.y);
            pa = dup2(a0.w); ffma2(acc[3][0], pa, bb.x); ffma2(acc[3][1], pa, bb.y);
            pa = dup2(a1.x); ffma2(acc[4][0], pa, bb.x); ffma2(acc[4][1], pa, bb.y);
            pa = dup2(a1.y); ffma2(acc[5][0], pa, bb.x); ffma2(acc[5][1], pa, bb.y);
            pa = dup2(a1.z); ffma2(acc[6][0], pa, bb.x); ffma2(acc[6][1], pa, bb.y);
            pa = dup2(a1.w); ffma2(acc[7][0], pa, bb.x); ffma2(acc[7][1], pa, bb.y);
        }

        float4 nj = *(const float4*)(nb + j0 + cg * 4);
#pragma unroll
        for (int r = 0; r < 8; r++) {
            float2 lo = unpk(acc[r][0]);
            float2 hi = unpk(acc[r][1]);
            float4 dv;
            dv.x = fmaf(-2.f, lo.x, nj.x);
            dv.y = fmaf(-2.f, lo.y, nj.y);
            dv.z = fmaf(-2.f, hi.x, nj.z);
            dv.w = fmaf(-2.f, hi.y, nj.w);
            *(float4*)(&stage[rg * 8 + r][cg * 4]) = dv;
        }
        __syncthreads();

#pragma unroll
        for (int q = 0; q < 8; q++) {
            int c4 = sq * 32 + q * 4;
            float4 v = *(const float4*)(&stage[srow][c4]);
            float m4 = fminf(fminf(v.x, v.y), fminf(v.z, v.w));
            if (m4 < bd[KNN - 1]) {
                float dv4[4] = {v.x, v.y, v.z, v.w};
#pragma unroll
                for (int e = 0; e < 4; e++) {
                    int j = j0 + c4 + e;
                    float d = dv4[e];
                    if (j != self && d < bd[KNN - 1]) {
                        bd[KNN - 1] = d; bj[KNN - 1] = j;
#pragma unroll
                        for (int p = KNN - 1; p > 0; p--) {
                            if (bd[p] < bd[p - 1]) {
                                float td = bd[p]; bd[p] = bd[p - 1]; bd[p - 1] = td;
                                int tj = bj[p]; bj[p] = bj[p - 1]; bj[p - 1] = tj;
                            }
                        }
                    }
                }
            }
        }
    }
    __syncthreads();

    float* mb = sm;
    {
        int base = (srow * 4 + sq) * 24;
#pragma unroll
        for (int p = 0; p < KNN; p++) {
            mb[base + p] = bd[p];
            ((int*)mb)[base + 12 + p] = bj[p];
        }
        mb[base + KNN] = 3.4e38f;
        ((int*)mb)[base + 12 + KNN] = 0x7fffffff;
    }
    __syncthreads();

    if (tid < 128) {
        int row = tid;
        int ptr[4] = {0, 0, 0, 0};
        int* outp = idxout + ((long long)(b * NPTS + i0 + row)) * KNN;
#pragma unroll
        for (int q = 0; q < KNN; q++) {
            float bestd = 3.4e38f; int bestj = 0x7fffffff; int bl = 0;
#pragma unroll
            for (int l = 0; l < 4; l++) {
                int base = (row * 4 + l) * 24;
                float dl = mb[base + ptr[l]];
                int jl = ((int*)mb)[base + 12 + ptr[l]];
                if (dl < bestd || (dl == bestd && jl < bestj)) {
                    bestd = dl; bestj = jl; bl = l;
                }
            }
            outp[q] = bestj;
            ptr[bl]++;
        }
    }
}

// ---------------- row squared norms ------------------------------------------------
__global__ void rownorms(const float* __restrict__ feat, int lda, int C,
                         float* __restrict__ nrm)
{
    int g = blockIdx.x * blockDim.x + threadIdx.x;
    const float* p = feat + (long long)g * lda;
    float s = 0.f;
    for (int c = 0; c < C; c += 4) {
        float4 v = *(const float4*)(p + c);
        s += v.x * v.x + v.y * v.y + v.z * v.z + v.w * v.w;
    }
    nrm[g] = s;
}

// ---------------- combine (float4) --------------------------------------------------
__global__ void combine2(const float* __restrict__ ycomb,
                         const int* __restrict__ idx, const float* __restrict__ s,
                         const float* __restrict__ t, float* __restrict__ outx, int O)
{
    int g = blockIdx.x * blockDim.x + threadIdx.x;
    int q = O >> 2;
    int bn = g / q;
    int o = (g - bn * q) << 2;
    const int* ip = idx + (long long)bn * KNN;
    int base = bn & ~2047;
    const int ld = 2 * O;
    float4 m = make_float4(-3.4e38f, -3.4e38f, -3.4e38f, -3.4e38f);
#pragma unroll
    for (int k = 0; k < KNN; k++) {
        int j = ip[k];
        float4 v = *(const float4*)(ycomb + (long long)(base + j) * ld + o);
        m.x = fmaxf(m.x, v.x); m.y = fmaxf(m.y, v.y);
        m.z = fmaxf(m.z, v.z); m.w = fmaxf(m.w, v.w);
    }
    float4 ydv = *(const float4*)(ycomb + (long long)bn * ld + o);
    float4 ybv = *(const float4*)(ycomb + (long long)bn * ld + O + o);
    float4 sv = *(const float4*)(s + o);
    float4 tv = *(const float4*)(t + o);
    float4 h;
    h.x = (m.x - ydv.x + ybv.x) * sv.x + tv.x;
    h.y = (m.y - ydv.y + ybv.y) * sv.y + tv.y;
    h.z = (m.z - ydv.z + ybv.z) * sv.z + tv.z;
    h.w = (m.w - ydv.w + ybv.w) * sv.w + tv.w;
    h.x = LRELU(h.x); h.y = LRELU(h.y); h.z = LRELU(h.z); h.w = LRELU(h.w);
    *(float4*)(outx + (long long)bn * 512 + o) = h;
}

// ---------------- input padding helpers -------------------------------------------
__global__ void pad_pts(const float* __restrict__ p, float* __restrict__ pp)
{
    int g = blockIdx.x * blockDim.x + threadIdx.x;
    pp[g * 4 + 0] = p[g * 3 + 0];
    pp[g * 4 + 1] = p[g * 3 + 1];
    pp[g * 4 + 2] = p[g * 3 + 2];
    pp[g * 4 + 3] = 0.f;
}
__global__ void pad_w1(const float* __restrict__ W1, float* __restrict__ wd,
                       float* __restrict__ wb)
{
    int o = threadIdx.x;
#pragma unroll
    for (int c = 0; c < 3; c++) {
        wd[o * 4 + c] = W1[o * 6 + c];
        wb[o * 4 + c] = W1[o * 6 + 3 + c];
    }
    wd[o * 4 + 3] = 0.f;
    wb[o * 4 + 3] = 0.f;
}

// ---------------- final 3 FC layers, fused (reads ordered-int pool) ----------------
__global__ void final_fc(const int* __restrict__ poolI,
                         const float* __restrict__ s5, const float* __restrict__ t5,
                         const float* __restrict__ Wf1, const float* __restrict__ sf1,
                         const float* __restrict__ tf1,
                         const float* __restrict__ Wf2, const float* __restrict__ bf2,
                         const float* __restrict__ sf2, const float* __restrict__ tf2,
                         const float* __restrict__ Wf3, const float* __restrict__ bf3,
                         float* __restrict__ out)
{
    __shared__ float sx[1024];
    __shared__ float h1[512];
    __shared__ float h2[256];
    int b = blockIdx.x, tid = threadIdx.x;
    {
        float v0 = ord2f(poolI[b * 1024 + tid]) * s5[tid] + t5[tid];
        float v1 = ord2f(poolI[b * 1024 + tid + 512]) * s5[tid + 512] + t5[tid + 512];
        sx[tid] = LRELU(v0);
        sx[tid + 512] = LRELU(v1);
    }
    __syncthreads();
    {
        const float* w = Wf1 + (long long)tid * 1024;
        float a0 = 0.f, a1 = 0.f, a2 = 0.f, a3 = 0.f;
        for (int c = 0; c < 1024; c += 4) {
            a0 = fmaf(w[c + 0], sx[c + 0], a0);
            a1 = fmaf(w[c + 1], sx[c + 1], a1);
            a2 = fmaf(w[c + 2], sx[c + 2], a2);
            a3 = fmaf(w[c + 3], sx[c + 3], a3);
        }
        float h = ((a0 + a1) + (a2 + a3)) * sf1[tid] + tf1[tid];
        h1[tid] = LRELU(h);
    }
    __syncthreads();
    if (tid < 256) {
        const float* w = Wf2 + (long long)tid * 512;
        float a0 = 0.f, a1 = 0.f, a2 = 0.f, a3 = 0.f;
        for (int c = 0; c < 512; c += 4) {
            a0 = fmaf(w[c + 0], h1[c + 0], a0);
            a1 = fmaf(w[c + 1], h1[c + 1], a1);
            a2 = fmaf(w[c + 2], h1[c + 2], a2);
            a3 = fmaf(w[c + 3], h1[c + 3], a3);
        }
        float h = (((a0 + a1) + (a2 + a3)) + bf2[tid]) * sf2[tid] + tf2[tid];
        h2[tid] = LRELU(h);
    }
    __syncthreads();
    if (tid < 3) {
        const float* w = Wf3 + (long long)tid * 256;
        float a = 0.f;
        for (int c = 0; c < 256; c++) a = fmaf(w[c], h2[c], a);
        out[b * 3 + tid] = a + bf3[tid];
    }
}

// ------------------------------- host side ---------------------------------------
extern "C" void kernel_launch(void* const* d_in, const int* in_sizes, int n_in,
                              void* d_out, int out_size)
{
    const float* points = (const float*)d_in[0];
    const float* W1 = (const float*)d_in[1];  const float* s1 = (const float*)d_in[2];  const float* t1 = (const float*)d_in[3];
    const float* W2 = (const float*)d_in[4];  const float* s2 = (const float*)d_in[5];  const float* t2 = (const float*)d_in[6];
    const float* W3 = (const float*)d_in[7];  const float* s3 = (const float*)d_in[8];  const float* t3 = (const float*)d_in[9];
    const float* W4 = (const float*)d_in[10]; const float* s4 = (const float*)d_in[11]; const float* t4 = (const float*)d_in[12];
    const float* W5 = (const float*)d_in[13]; const float* s5 = (const float*)d_in[14]; const float* t5 = (const float*)d_in[15];
    const float* Wf1 = (const float*)d_in[16]; const float* sf1 = (const float*)d_in[17]; const float* tf1 = (const float*)d_in[18];
    const float* Wf2 = (const float*)d_in[19]; const float* bf2 = (const float*)d_in[20];
    const float* sf2 = (const float*)d_in[21]; const float* tf2 = (const float*)d_in[22];
    const float* Wf3 = (const float*)d_in[23]; const float* bf3 = (const float*)d_in[24];

    float *xcat, *nrm, *ycomb, *pts, *w1d, *w1b;
    int *idx, *poolI;
    __nv_bfloat16 *a3, *ag, *w3, *wl;
    cudaGetSymbolAddress((void**)&xcat,  g_xcat);
    cudaGetSymbolAddress((void**)&nrm,   g_nrm);
    cudaGetSymbolAddress((void**)&idx,   g_idx);
    cudaGetSymbolAddress((void**)&ycomb, g_ycomb);
    cudaGetSymbolAddress((void**)&poolI, g_poolI);
    cudaGetSymbolAddress((void**)&pts,   g_pts);
    cudaGetSymbolAddress((void**)&w1d,   g_w1d);
    cudaGetSymbolAddress((void**)&w1b,   g_w1b);
    cudaGetSymbolAddress((void**)&a3,    g_a3);
    cudaGetSymbolAddress((void**)&ag,    g_ag);
    cudaGetSymbolAddress((void**)&w3,    g_w3);
    cudaGetSymbolAddress((void**)&wl,    g_wl);

    cudaFuncSetAttribute(gramknn, cudaFuncAttributeMaxDynamicSharedMemorySize,
                         GK_SMEM_BYTES);

    static cudaStream_t sKnn = nullptr;
    static cudaEvent_t evFork[8], evJoin[8];
    if (!sKnn) {
        cudaStreamCreateWithFlags(&sKnn, cudaStreamNonBlocking);
        for (int i = 0; i < 8; i++) {
            cudaEventCreateWithFlags(&evFork[i], cudaEventDisableTiming);
            cudaEventCreateWithFlags(&evJoin[i], cudaEventDisableTiming);
        }
    }
    int ev = 0;

    const int BN = BN_TOT;   // 16384

    pad_pts<<<BN / 256, 256>>>(points, pts);
    pad_w1<<<1, 64>>>(W1, w1d, w1b);
    pool_init<<<(NB * 1024) / 256, 256>>>(poolI);
    // W5 weight split: no deps -> hoisted to start
    split3_fast<<<(1024 * 512) / 256, 256>>>(W5, 512, 9, w3, 0, 1024LL * 512);

    auto lg2 = [](int c) { int l = 0; while ((1 << l) < c) l++; return l; };

    // fork-join edge layer: knn chain on sKnn, gemm chain on main (NULL) stream
    auto edge = [&](const float* feat, int lda, int C, int O,
                    const float* Wd, const float* Wb, int ldw,
                    const float* s, const float* t, int coff) {
        cudaEventRecord(evFork[ev], 0);
        cudaStreamWaitEvent(sKnn, evFork[ev], 0);
        rownorms<<<BN / 256, 256, 0, sKnn>>>(feat, lda, C, nrm);
        gramknn<<<dim3(16, NB), 512, GK_SMEM_BYTES, sKnn>>>(feat, lda, C, nrm, idx);
        cudaEventRecord(evJoin[ev], sKnn);

        int Kp;
        if (C >= 64) {
            Kp = 3 * C;
            int l = lg2(C);
            split3_fast<<<(unsigned)(((long long)BN * C) / 256), 256>>>(
                feat, lda, l, ag, 1, (long long)BN * C);
            split3_fast<<<(unsigned)(((long long)O * C + 255) / 256), 256>>>(
                Wd, ldw, l, wl, 0, (long long)O * C);
            split3_fast<<<(unsigned)(((long long)O * C + 255) / 256), 256>>>(
                Wb, ldw, l, wl + (long long)O * Kp, 0, (long long)O * C);
        } else {
            Kp = 32;
            long long ta = (long long)BN * Kp;
            split3_feat<<<(unsigned)((ta + 255) / 256), 256>>>(feat, lda, C, Kp, ag, ta);
            long long tw = (long long)O * Kp;
            split3_w<<<(unsigned)((tw + 255) / 256), 256>>>(Wd, ldw, C, Kp, wl, 0, tw);
            split3_w<<<(unsigned)((tw + 255) / 256), 256>>>(Wb, ldw, C, Kp, wl, O, tw);
        }
        int N = 2 * O;
        hgemm<<<dim3(BN / 128, N / 128), 256>>>(ag, wl, ycomb, BN, N, Kp, N, nullptr);

        cudaStreamWaitEvent(0, evJoin[ev], 0);
        ev++;
        combine2<<<(BN * (O / 4)) / 256, 256>>>(ycomb, idx, s, t, xcat + coff, O);
    };

    edge(pts,        4,   4,   64, w1d, w1b,      4,   s1, t1, 0);
    edge(xcat + 0,   512, 64,  64, W2,  W2 + 64,  128, s2, t2, 64);
    edge(xcat + 64,  512, 64,  128, W3, W3 + 64,  128, s3, t3, 128);
    edge(xcat + 128, 512, 128, 256, W4, W4 + 128, 256, s4, t4, 256);

    // point MLP with fused global max-pool (raw values; affine+lrelu in final_fc)
    {
        const int C = 512, O = 1024, Kp = 1536;
        split3_fast<<<(unsigned)(((long long)BN * C) / 256), 256>>>(
            xcat, 512, 9, a3, 1, (long long)BN * C);
        hgemm<<<dim3(BN / 128, O / 128), 256>>>(a3, w3, nullptr, BN, O, Kp, O, poolI);
    }
    final_fc<<<NB, 512>>>(poolI, s5, t5, Wf1, sf1, tf1, Wf2, bf2, sf2, tf2,
                          Wf3, bf3, (float*)d_out);
}